// round 9
// baseline (speedup 1.0000x reference)
#include <cuda_runtime.h>
#include <cuda_fp16.h>
#include <cstdint>
#include <cstddef>

// Problem constants
#define BATCH 8
#define LEN   4096
#define IND   512
#define ST    256
#define OUTD  512

#define CHUNK 32
#define NCH   (LEN / CHUNK)   // 128

// Scratch in device globals (no allocation allowed)
__device__ float g_uB[(size_t)BATCH * LEN * ST];      // 32 MB (fp32 scan input)
__device__ half  g_uh[(size_t)BATCH * LEN * IND];     // 32 MB (u as fp16)
__device__ half  g_xh[(size_t)BATCH * LEN * ST];      // 16 MB (x as fp16)
__device__ float g_carry[BATCH * NCH * ST];
__device__ float g_init [BATCH * NCH * ST];
__device__ half  g_Bh[IND * ST], g_Bl[IND * ST];      // B split
__device__ half  g_Ch[ST * OUTD], g_Cl[ST * OUTD];    // C split

// ---------------------------------------------------------------------------
// HMMA asymmetric-split GEMM, all-half inputs:
//   Cm[M,N](fp32) = Ah[M,K] @ (Bh + Bl)[K,N]
// CTA tile 128x256x32, 8 warps (2m x 4n), warp tile 64x64, fp32 accum,
// cp.async double-buffered staging.
// ---------------------------------------------------------------------------
#define BM 128
#define BN 256
#define BKK 32
#define ALD 40     // A smem leading dim (halves), pad 32->40
#define BLD 264    // B smem leading dim (halves), pad 256->264
#define A_B  (BM * ALD * 2)              // 10240 bytes
#define B_B  (BKK * BLD * 2)             // 16896 bytes
#define STAGE_B (A_B + 2 * B_B)          // 44032 bytes
#define GEMM_SMEM (2 * STAGE_B)          // 88064 bytes

__device__ __forceinline__ uint32_t smem_u32(const void* p) {
    uint32_t a;
    asm("{ .reg .u64 t; cvta.to.shared.u64 t, %1; cvt.u32.u64 %0, t; }"
        : "=r"(a) : "l"(p));
    return a;
}

#define CP16(saddr, gptr) \
    asm volatile("cp.async.cg.shared.global [%0], [%1], 16;" \
        :: "r"(saddr), "l"(gptr))
#define CP_COMMIT() asm volatile("cp.async.commit_group;" ::: "memory")
#define CP_WAIT(n)  asm volatile("cp.async.wait_group %0;" :: "n"(n) : "memory")

#define LDSM_X4(r, addr) \
    asm volatile("ldmatrix.sync.aligned.m8n8.x4.shared.b16 {%0,%1,%2,%3}, [%4];" \
        : "=r"((r)[0]), "=r"((r)[1]), "=r"((r)[2]), "=r"((r)[3]) : "r"(addr))

#define LDSM_X4T(r, addr) \
    asm volatile("ldmatrix.sync.aligned.m8n8.x4.trans.shared.b16 {%0,%1,%2,%3}, [%4];" \
        : "=r"((r)[0]), "=r"((r)[1]), "=r"((r)[2]), "=r"((r)[3]) : "r"(addr))

#define MMA16816(d, a, b0, b1) \
    asm volatile("mma.sync.aligned.m16n8k16.row.col.f32.f16.f16.f32 " \
        "{%0,%1,%2,%3}, {%4,%5,%6,%7}, {%8,%9}, {%0,%1,%2,%3};" \
        : "+f"((d)[0]), "+f"((d)[1]), "+f"((d)[2]), "+f"((d)[3]) \
        : "r"((a)[0]), "r"((a)[1]), "r"((a)[2]), "r"((a)[3]), \
          "r"(b0), "r"(b1))

__global__ __launch_bounds__(256, 1)
void gemm_hmma_h(const half* __restrict__ Ag_, const half* __restrict__ Bhg,
                 const half* __restrict__ Blg, float* __restrict__ Cm,
                 int M, int N, int K) {
    extern __shared__ half sm[];
    const uint32_t sbase = smem_u32(sm);
    const int tid = threadIdx.x;
    const int lane = tid & 31, wid = tid >> 5;
    const int warp_m = wid >> 2;  // 0..1 (64 rows each)
    const int warp_n = wid & 3;   // 0..3 (64 cols each)
    const int rowBase = blockIdx.y * BM;
    const int colBase = blockIdx.x * BN;

    // Staging maps
    const int ar = tid >> 1, ac = (tid & 1) * 16;   // A: 128 rows x 32 halves
    const int br = tid >> 3, bc = (tid & 7) * 32;   // B: 32 rows x 256 halves

    const half* Ag  = Ag_ + (size_t)(rowBase + ar) * K + ac;
    const half* Bg0 = Bhg + (size_t)br * N + colBase + bc;
    const half* Bg1 = Blg + (size_t)br * N + colBase + bc;

    const uint32_t sAoff = (uint32_t)(ar * ALD + ac) * 2;
    const uint32_t sBoff = (uint32_t)A_B + (uint32_t)(br * BLD + bc) * 2;

    float acc[4][8][4] = {};

    // prologue: stage 0
    {
        uint32_t base = sbase;
        CP16(base + sAoff,      Ag);
        CP16(base + sAoff + 16, Ag + 8);
        #pragma unroll
        for (int i = 0; i < 4; i++) {
            CP16(base + sBoff + i * 16,       Bg0 + i * 8);
            CP16(base + sBoff + B_B + i * 16, Bg1 + i * 8);
        }
    }
    CP_COMMIT();

    const int nst = K / BKK;
    for (int s = 0; s < nst; s++) {
        const int cur = s & 1;
        if (s + 1 < nst) {
            const int k0 = (s + 1) * BKK;
            uint32_t base = sbase + (cur ^ 1) * STAGE_B;
            const half* a  = Ag + k0;
            const half* b0 = Bg0 + (size_t)k0 * N;
            const half* b1 = Bg1 + (size_t)k0 * N;
            CP16(base + sAoff,      a);
            CP16(base + sAoff + 16, a + 8);
            #pragma unroll
            for (int i = 0; i < 4; i++) {
                CP16(base + sBoff + i * 16,       b0 + i * 8);
                CP16(base + sBoff + B_B + i * 16, b1 + i * 8);
            }
            CP_COMMIT();
            CP_WAIT(1);
        } else {
            CP_WAIT(0);
        }
        __syncthreads();

        // compute on stage cur
        {
            const uint32_t base = sbase + cur * STAGE_B;
            #pragma unroll
            for (int k16 = 0; k16 < 2; k16++) {
                uint32_t ah[4][4], bh[4][4], bl[4][4];
                const int arow = warp_m * 64 + (lane & 15);
                const int acol = k16 * 16 + (lane >> 4) * 8;
                #pragma unroll
                for (int mi = 0; mi < 4; mi++)
                    LDSM_X4(ah[mi], base + (uint32_t)((arow + mi * 16) * ALD + acol) * 2);
                const int brow = k16 * 16 + (lane & 15);
                const int bcol = warp_n * 64 + (lane >> 4) * 8;
                #pragma unroll
                for (int ni = 0; ni < 4; ni++) {
                    uint32_t boff = (uint32_t)A_B + (uint32_t)(brow * BLD + bcol + ni * 16) * 2;
                    LDSM_X4T(bh[ni], base + boff);
                    LDSM_X4T(bl[ni], base + boff + (uint32_t)B_B);
                }
                #pragma unroll
                for (int mi = 0; mi < 4; mi++)
                    #pragma unroll
                    for (int nj = 0; nj < 8; nj++) {
                        const int ni = nj >> 1, ro = (nj & 1) * 2;
                        MMA16816(acc[mi][nj], ah[mi], bh[ni][ro], bh[ni][ro + 1]);
                        MMA16816(acc[mi][nj], ah[mi], bl[ni][ro], bl[ni][ro + 1]);
                    }
            }
        }
        __syncthreads();
    }

    // Epilogue
    const int g = lane >> 2;
    const int cc = (lane & 3) * 2;
    #pragma unroll
    for (int mi = 0; mi < 4; mi++) {
        const int r0 = rowBase + warp_m * 64 + mi * 16 + g;
        #pragma unroll
        for (int nj = 0; nj < 8; nj++) {
            const int c0 = colBase + warp_n * 64 + nj * 8 + cc;
            *(float2*)&Cm[(size_t)r0 * N + c0]       = make_float2(acc[mi][nj][0], acc[mi][nj][1]);
            *(float2*)&Cm[(size_t)(r0 + 8) * N + c0] = make_float2(acc[mi][nj][2], acc[mi][nj][3]);
        }
    }
}

// ---------------------------------------------------------------------------
// fp32 -> fp16 bulk convert (8 elems/thread)
// ---------------------------------------------------------------------------
__global__ __launch_bounds__(256)
void cvt_half_kernel(const float* __restrict__ in, half* __restrict__ out, int n) {
    int i = (blockIdx.x * 256 + threadIdx.x) * 8;
    if (i >= n) return;
    float4 v0 = *(const float4*)(in + i);
    float4 v1 = *(const float4*)(in + i + 4);
    half2 h[4];
    h[0] = __floats2half2_rn(v0.x, v0.y);
    h[1] = __floats2half2_rn(v0.z, v0.w);
    h[2] = __floats2half2_rn(v1.x, v1.y);
    h[3] = __floats2half2_rn(v1.z, v1.w);
    *(uint4*)(out + i) = *(uint4*)h;
}

// ---------------------------------------------------------------------------
// fp32 -> (hi, lo) fp16 split (8 elems/thread) — for weights
// ---------------------------------------------------------------------------
__global__ __launch_bounds__(256)
void split_kernel(const float* __restrict__ in, half* __restrict__ hi,
                  half* __restrict__ lo, int n) {
    int i = (blockIdx.x * 256 + threadIdx.x) * 8;
    if (i >= n) return;
    float v[8];
    *(float4*)&v[0] = *(const float4*)(in + i);
    *(float4*)&v[4] = *(const float4*)(in + i + 4);
    half h[8], l[8];
    #pragma unroll
    for (int j = 0; j < 8; j++) {
        h[j] = __float2half_rn(v[j]);
        l[j] = __float2half_rn(v[j] - __half2float(h[j]));
    }
    *(uint4*)(hi + i) = *(uint4*)h;
    *(uint4*)(lo + i) = *(uint4*)l;
}

// ---------------------------------------------------------------------------
// Scan pass 1: per-chunk carry with zero initial state.
// ---------------------------------------------------------------------------
__global__ __launch_bounds__(ST / 2)
void scan1_kernel(const float* __restrict__ A) {
    const int n2 = threadIdx.x;
    const int c = blockIdx.x % NCH;
    const int b = blockIdx.x / NCH;
    const float2 a = ((const float2*)A)[n2];
    const float2* p = (const float2*)(g_uB + ((size_t)(b * LEN + c * CHUNK)) * ST) + n2;
    float2 s = make_float2(0.0f, 0.0f);
    #pragma unroll
    for (int t = 0; t < CHUNK; t++) {
        float2 v = p[(size_t)t * (ST / 2)];
        s.x = fmaf(a.x, s.x, v.x);
        s.y = fmaf(a.y, s.y, v.y);
    }
    ((float2*)g_carry)[(b * NCH + c) * (ST / 2) + n2] = s;
}

// ---------------------------------------------------------------------------
// Scan pass 2: inter-chunk exclusive prefix combine.
// ---------------------------------------------------------------------------
__global__ __launch_bounds__(ST / 2)
void scan2_kernel(const float* __restrict__ A, const float* __restrict__ x0) {
    const int n2 = threadIdx.x;
    const int b = blockIdx.x;
    const float2 a = ((const float2*)A)[n2];
    float2 aL = a;
    #pragma unroll
    for (int i = 0; i < 5; i++) { aL.x *= aL.x; aL.y *= aL.y; }   // a^32
    float2 s = ((const float2*)x0)[b * (ST / 2) + n2];
    #pragma unroll
    for (int c = 0; c < NCH; c++) {
        ((float2*)g_init)[(b * NCH + c) * (ST / 2) + n2] = s;
        float2 cv = ((const float2*)g_carry)[(b * NCH + c) * (ST / 2) + n2];
        s.x = fmaf(aL.x, s.x, cv.x);
        s.y = fmaf(aL.y, s.y, cv.y);
    }
}

// ---------------------------------------------------------------------------
// Scan pass 3: rescan per chunk from true init, write x as fp16 (GEMM2 input).
// ---------------------------------------------------------------------------
__global__ __launch_bounds__(ST / 2)
void scan3_kernel(const float* __restrict__ A, float* __restrict__ xlast) {
    const int n2 = threadIdx.x;
    const int c = blockIdx.x % NCH;
    const int b = blockIdx.x / NCH;
    const float2 a = ((const float2*)A)[n2];
    float2 s = ((const float2*)g_init)[(b * NCH + c) * (ST / 2) + n2];
    const size_t base = ((size_t)(b * LEN + c * CHUNK)) * (ST / 2) + n2;
    const float2* pin = (const float2*)g_uB;
    half2* pout = (half2*)g_xh;
    #pragma unroll
    for (int t = 0; t < CHUNK; t++) {
        float2 v = pin[base + (size_t)t * (ST / 2)];
        s.x = fmaf(a.x, s.x, v.x);
        s.y = fmaf(a.y, s.y, v.y);
        pout[base + (size_t)t * (ST / 2)] = __floats2half2_rn(s.x, s.y);
    }
    if (c == NCH - 1) {
        ((float2*)xlast)[b * (ST / 2) + n2] = s;
    }
}

// ---------------------------------------------------------------------------
// kernel_launch
// Inputs: u [8,4096,512], x0 [8,256], A [256], B [512,256], C [256,512]
// Output: y [8,4096,512] flattened, then x_last [8,256].
// ---------------------------------------------------------------------------
extern "C" void kernel_launch(void* const* d_in, const int* in_sizes, int n_in,
                              void* d_out, int out_size) {
    const float* u  = (const float*)d_in[0];
    const float* x0 = (const float*)d_in[1];
    const float* A  = (const float*)d_in[2];
    const float* B  = (const float*)d_in[3];
    const float* C  = (const float*)d_in[4];

    float* y = (float*)d_out;
    float* xlast = y + (size_t)BATCH * LEN * OUTD;

    float *uB_ptr;
    half *uh_ptr, *xh_ptr, *Bh_ptr, *Bl_ptr, *Ch_ptr, *Cl_ptr;
    cudaGetSymbolAddress((void**)&uB_ptr, g_uB);
    cudaGetSymbolAddress((void**)&uh_ptr, g_uh);
    cudaGetSymbolAddress((void**)&xh_ptr, g_xh);
    cudaGetSymbolAddress((void**)&Bh_ptr, g_Bh);
    cudaGetSymbolAddress((void**)&Bl_ptr, g_Bl);
    cudaGetSymbolAddress((void**)&Ch_ptr, g_Ch);
    cudaGetSymbolAddress((void**)&Cl_ptr, g_Cl);

    cudaFuncSetAttribute(gemm_hmma_h, cudaFuncAttributeMaxDynamicSharedMemorySize, GEMM_SMEM);

    const int M = BATCH * LEN;   // 32768

    // Pre-passes: u -> fp16; split weights once
    {
        int n = M * IND;
        cvt_half_kernel<<<n / (256 * 8), 256>>>(u, uh_ptr, n);
        split_kernel<<<(IND * ST) / (256 * 8), 256>>>(B, Bh_ptr, Bl_ptr, IND * ST);
        split_kernel<<<(ST * OUTD) / (256 * 8), 256>>>(C, Ch_ptr, Cl_ptr, ST * OUTD);
    }

    // GEMM1: uB = uh @ (Bh+Bl)   [32768,512] @ [512,256]
    {
        dim3 grid(ST / BN, M / BM);
        gemm_hmma_h<<<grid, 256, GEMM_SMEM>>>(uh_ptr, Bh_ptr, Bl_ptr, uB_ptr, M, ST, IND);
    }

    // Scan
    scan1_kernel<<<BATCH * NCH, ST / 2>>>(A);
    scan2_kernel<<<BATCH, ST / 2>>>(A, x0);
    scan3_kernel<<<BATCH * NCH, ST / 2>>>(A, xlast);

    // GEMM2: y = xh @ (Ch+Cl)    [32768,256] @ [256,512]
    {
        dim3 grid(OUTD / BN, M / BM);
        gemm_hmma_h<<<grid, 256, GEMM_SMEM>>>(xh_ptr, Ch_ptr, Cl_ptr, y, M, OUTD, ST);
    }
}

// round 10
// speedup vs baseline: 1.0741x; 1.0741x over previous
#include <cuda_runtime.h>
#include <cuda_fp16.h>
#include <cstdint>
#include <cstddef>

// Problem constants
#define BATCH 8
#define LEN   4096
#define IND   512
#define ST    256
#define OUTD  512

#define CHUNK 32
#define NCH   (LEN / CHUNK)   // 128

// Scratch in device globals (no allocation allowed)
__device__ float g_uB[(size_t)BATCH * LEN * ST];      // 32 MB (fp32 scan input)
__device__ half  g_uh[(size_t)BATCH * LEN * IND];     // 32 MB (u as fp16)
__device__ half  g_xh[(size_t)BATCH * LEN * ST];      // 16 MB (x as fp16)
__device__ float g_carry[BATCH * NCH * ST];
__device__ float g_init [BATCH * NCH * ST];
__device__ half  g_Bh[IND * ST], g_Bl[IND * ST];      // B split
__device__ half  g_Ch[ST * OUTD], g_Cl[ST * OUTD];    // C split

// ---------------------------------------------------------------------------
// HMMA asymmetric-split GEMM, all-half inputs:
//   Cm[M,N](fp32) = Ah[M,K] @ (Bh + Bl)[K,N]
// CTA tile 128x128x32, 8 warps as 2m x 4n, warp tile 64x32 (A-heavy aspect:
// B traffic counts twice due to hi+lo, so short n / tall m minimizes LDSM
// bytes per MMA). fp32 accumulate, register-prefetch double buffering.
// ---------------------------------------------------------------------------
#define BM 128
#define BN 128
#define BKK 32
#define ALD 40    // A smem leading dim in halves (pad 32->40)
#define BLD 136   // B smem leading dim in halves (pad 128->136)
#define A_SZ (BM * ALD)                 // 5120 halves
#define B_SZ (BKK * BLD)                // 4352 halves
#define STAGE_H (A_SZ + 2 * B_SZ)       // 13824 halves
#define GEMM_SMEM (2 * STAGE_H * 2)     // 55296 bytes

__device__ __forceinline__ uint32_t smem_u32(const void* p) {
    uint32_t a;
    asm("{ .reg .u64 t; cvta.to.shared.u64 t, %1; cvt.u32.u64 %0, t; }"
        : "=r"(a) : "l"(p));
    return a;
}

#define LDSM_X4(r, addr) \
    asm volatile("ldmatrix.sync.aligned.m8n8.x4.shared.b16 {%0,%1,%2,%3}, [%4];" \
        : "=r"((r)[0]), "=r"((r)[1]), "=r"((r)[2]), "=r"((r)[3]) : "r"(addr))

#define LDSM_X4T(r, addr) \
    asm volatile("ldmatrix.sync.aligned.m8n8.x4.trans.shared.b16 {%0,%1,%2,%3}, [%4];" \
        : "=r"((r)[0]), "=r"((r)[1]), "=r"((r)[2]), "=r"((r)[3]) : "r"(addr))

#define MMA16816(d, a, b0, b1) \
    asm volatile("mma.sync.aligned.m16n8k16.row.col.f32.f16.f16.f32 " \
        "{%0,%1,%2,%3}, {%4,%5,%6,%7}, {%8,%9}, {%0,%1,%2,%3};" \
        : "+f"((d)[0]), "+f"((d)[1]), "+f"((d)[2]), "+f"((d)[3]) \
        : "r"((a)[0]), "r"((a)[1]), "r"((a)[2]), "r"((a)[3]), \
          "r"(b0), "r"(b1))

__global__ __launch_bounds__(256)
void gemm_hmma_h(const half* __restrict__ Ag_, const half* __restrict__ Bhg,
                 const half* __restrict__ Blg, float* __restrict__ Cm,
                 int M, int N, int K) {
    extern __shared__ half sm[];
    const int tid = threadIdx.x;
    const int lane = tid & 31, wid = tid >> 5;
    const int warp_m = wid >> 2;  // 0..1  -> 64 rows each
    const int warp_n = wid & 3;   // 0..3  -> 32 cols each
    const int rowBase = blockIdx.y * BM;
    const int colBase = blockIdx.x * BN;

    // Loader mapping: per thread 16 halves (2 x uint4) per tile
    const int ar = tid >> 1, ac = (tid & 1) * 16;   // A: 128 rows x 32 cols
    const int br = tid >> 3, bc = (tid & 7) * 16;   // B: 32 rows x 128 cols

    const half* Ag  = Ag_ + (size_t)(rowBase + ar) * K + ac;
    const half* Bg0 = Bhg + (size_t)br * N + colBase + bc;
    const half* Bg1 = Blg + (size_t)br * N + colBase + bc;

    float acc[4][4][4] = {};

    // prologue: stage 0
    {
        half* Ah = sm;
        half* Bh = Ah + A_SZ;
        half* Bl = Bh + B_SZ;
        const uint4* pA = (const uint4*)Ag;
        const uint4* p0 = (const uint4*)Bg0;
        const uint4* p1 = (const uint4*)Bg1;
        *(uint4*)&Ah[ar * ALD + ac]       = pA[0];
        *(uint4*)&Ah[ar * ALD + ac + 8]   = pA[1];
        *(uint4*)&Bh[br * BLD + bc]       = p0[0];
        *(uint4*)&Bh[br * BLD + bc + 8]   = p0[1];
        *(uint4*)&Bl[br * BLD + bc]       = p1[0];
        *(uint4*)&Bl[br * BLD + bc + 8]   = p1[1];
    }
    __syncthreads();

    const int nst = K / BKK;
    for (int s = 0; s < nst; s++) {
        const int cur = s & 1;
        const bool more = (s + 1 < nst);
        uint4 pa[2], pbh[2], pbl[2];
        if (more) {
            const uint4* pA = (const uint4*)(Ag + (s + 1) * BKK);
            const uint4* p0 = (const uint4*)(Bg0 + (size_t)(s + 1) * BKK * N);
            const uint4* p1 = (const uint4*)(Blg + (size_t)((s + 1) * BKK + br) * N + colBase + bc);
            pa[0] = pA[0];  pa[1] = pA[1];
            pbh[0] = p0[0]; pbh[1] = p0[1];
            pbl[0] = p1[0]; pbl[1] = p1[1];
        }

        // compute on stage cur
        {
            half* Ah = sm + (size_t)cur * STAGE_H;
            half* Bh = Ah + A_SZ;
            half* Bl = Bh + B_SZ;
            #pragma unroll
            for (int k16 = 0; k16 < 2; k16++) {
                uint32_t ah[4][4], bh[2][4], bl[2][4];
                const int arow = warp_m * 64 + (lane & 15);
                const int acol = k16 * 16 + (lane >> 4) * 8;
                #pragma unroll
                for (int mi = 0; mi < 4; mi++)
                    LDSM_X4(ah[mi], smem_u32(&Ah[(arow + mi * 16) * ALD + acol]));
                const int brow = k16 * 16 + (lane & 15);
                const int bcol = warp_n * 32 + (lane >> 4) * 8;
                #pragma unroll
                for (int ni = 0; ni < 2; ni++) {
                    LDSM_X4T(bh[ni], smem_u32(&Bh[brow * BLD + bcol + ni * 16]));
                    LDSM_X4T(bl[ni], smem_u32(&Bl[brow * BLD + bcol + ni * 16]));
                }
                #pragma unroll
                for (int mi = 0; mi < 4; mi++)
                    #pragma unroll
                    for (int nj = 0; nj < 4; nj++) {
                        const int ni = nj >> 1, ro = (nj & 1) * 2;
                        MMA16816(acc[mi][nj], ah[mi], bh[ni][ro], bh[ni][ro + 1]);
                        MMA16816(acc[mi][nj], ah[mi], bl[ni][ro], bl[ni][ro + 1]);
                    }
            }
        }

        if (more) {
            half* Ah = sm + (size_t)(cur ^ 1) * STAGE_H;
            half* Bh = Ah + A_SZ;
            half* Bl = Bh + B_SZ;
            *(uint4*)&Ah[ar * ALD + ac]     = pa[0];
            *(uint4*)&Ah[ar * ALD + ac + 8] = pa[1];
            *(uint4*)&Bh[br * BLD + bc]     = pbh[0];
            *(uint4*)&Bh[br * BLD + bc + 8] = pbh[1];
            *(uint4*)&Bl[br * BLD + bc]     = pbl[0];
            *(uint4*)&Bl[br * BLD + bc + 8] = pbl[1];
        }
        __syncthreads();
    }

    // Epilogue
    const int g = lane >> 2;
    const int cc = (lane & 3) * 2;
    #pragma unroll
    for (int mi = 0; mi < 4; mi++) {
        const int r0 = rowBase + warp_m * 64 + mi * 16 + g;
        #pragma unroll
        for (int nj = 0; nj < 4; nj++) {
            const int c0 = colBase + warp_n * 32 + nj * 8 + cc;
            *(float2*)&Cm[(size_t)r0 * N + c0]       = make_float2(acc[mi][nj][0], acc[mi][nj][1]);
            *(float2*)&Cm[(size_t)(r0 + 8) * N + c0] = make_float2(acc[mi][nj][2], acc[mi][nj][3]);
        }
    }
}

// ---------------------------------------------------------------------------
// fp32 -> fp16 bulk convert (8 elems/thread)
// ---------------------------------------------------------------------------
__global__ __launch_bounds__(256)
void cvt_half_kernel(const float* __restrict__ in, half* __restrict__ out, int n) {
    int i = (blockIdx.x * 256 + threadIdx.x) * 8;
    if (i >= n) return;
    float4 v0 = *(const float4*)(in + i);
    float4 v1 = *(const float4*)(in + i + 4);
    half2 h[4];
    h[0] = __floats2half2_rn(v0.x, v0.y);
    h[1] = __floats2half2_rn(v0.z, v0.w);
    h[2] = __floats2half2_rn(v1.x, v1.y);
    h[3] = __floats2half2_rn(v1.z, v1.w);
    *(uint4*)(out + i) = *(uint4*)h;
}

// ---------------------------------------------------------------------------
// fp32 -> (hi, lo) fp16 split (8 elems/thread) — for weights
// ---------------------------------------------------------------------------
__global__ __launch_bounds__(256)
void split_kernel(const float* __restrict__ in, half* __restrict__ hi,
                  half* __restrict__ lo, int n) {
    int i = (blockIdx.x * 256 + threadIdx.x) * 8;
    if (i >= n) return;
    float v[8];
    *(float4*)&v[0] = *(const float4*)(in + i);
    *(float4*)&v[4] = *(const float4*)(in + i + 4);
    half h[8], l[8];
    #pragma unroll
    for (int j = 0; j < 8; j++) {
        h[j] = __float2half_rn(v[j]);
        l[j] = __float2half_rn(v[j] - __half2float(h[j]));
    }
    *(uint4*)(hi + i) = *(uint4*)h;
    *(uint4*)(lo + i) = *(uint4*)l;
}

// ---------------------------------------------------------------------------
// Scan pass 1: per-chunk carry with zero initial state.
// ---------------------------------------------------------------------------
__global__ __launch_bounds__(ST / 2)
void scan1_kernel(const float* __restrict__ A) {
    const int n2 = threadIdx.x;
    const int c = blockIdx.x % NCH;
    const int b = blockIdx.x / NCH;
    const float2 a = ((const float2*)A)[n2];
    const float2* p = (const float2*)(g_uB + ((size_t)(b * LEN + c * CHUNK)) * ST) + n2;
    float2 s = make_float2(0.0f, 0.0f);
    #pragma unroll
    for (int t = 0; t < CHUNK; t++) {
        float2 v = p[(size_t)t * (ST / 2)];
        s.x = fmaf(a.x, s.x, v.x);
        s.y = fmaf(a.y, s.y, v.y);
    }
    ((float2*)g_carry)[(b * NCH + c) * (ST / 2) + n2] = s;
}

// ---------------------------------------------------------------------------
// Scan pass 2: inter-chunk exclusive prefix combine.
// ---------------------------------------------------------------------------
__global__ __launch_bounds__(ST / 2)
void scan2_kernel(const float* __restrict__ A, const float* __restrict__ x0) {
    const int n2 = threadIdx.x;
    const int b = blockIdx.x;
    const float2 a = ((const float2*)A)[n2];
    float2 aL = a;
    #pragma unroll
    for (int i = 0; i < 5; i++) { aL.x *= aL.x; aL.y *= aL.y; }   // a^32
    float2 s = ((const float2*)x0)[b * (ST / 2) + n2];
    #pragma unroll
    for (int c = 0; c < NCH; c++) {
        ((float2*)g_init)[(b * NCH + c) * (ST / 2) + n2] = s;
        float2 cv = ((const float2*)g_carry)[(b * NCH + c) * (ST / 2) + n2];
        s.x = fmaf(aL.x, s.x, cv.x);
        s.y = fmaf(aL.y, s.y, cv.y);
    }
}

// ---------------------------------------------------------------------------
// Scan pass 3: rescan per chunk from true init, write x as fp16 (GEMM2 input).
// ---------------------------------------------------------------------------
__global__ __launch_bounds__(ST / 2)
void scan3_kernel(const float* __restrict__ A, float* __restrict__ xlast) {
    const int n2 = threadIdx.x;
    const int c = blockIdx.x % NCH;
    const int b = blockIdx.x / NCH;
    const float2 a = ((const float2*)A)[n2];
    float2 s = ((const float2*)g_init)[(b * NCH + c) * (ST / 2) + n2];
    const size_t base = ((size_t)(b * LEN + c * CHUNK)) * (ST / 2) + n2;
    const float2* pin = (const float2*)g_uB;
    half2* pout = (half2*)g_xh;
    #pragma unroll
    for (int t = 0; t < CHUNK; t++) {
        float2 v = pin[base + (size_t)t * (ST / 2)];
        s.x = fmaf(a.x, s.x, v.x);
        s.y = fmaf(a.y, s.y, v.y);
        pout[base + (size_t)t * (ST / 2)] = __floats2half2_rn(s.x, s.y);
    }
    if (c == NCH - 1) {
        ((float2*)xlast)[b * (ST / 2) + n2] = s;
    }
}

// ---------------------------------------------------------------------------
// kernel_launch
// Inputs: u [8,4096,512], x0 [8,256], A [256], B [512,256], C [256,512]
// Output: y [8,4096,512] flattened, then x_last [8,256].
// ---------------------------------------------------------------------------
extern "C" void kernel_launch(void* const* d_in, const int* in_sizes, int n_in,
                              void* d_out, int out_size) {
    const float* u  = (const float*)d_in[0];
    const float* x0 = (const float*)d_in[1];
    const float* A  = (const float*)d_in[2];
    const float* B  = (const float*)d_in[3];
    const float* C  = (const float*)d_in[4];

    float* y = (float*)d_out;
    float* xlast = y + (size_t)BATCH * LEN * OUTD;

    float *uB_ptr;
    half *uh_ptr, *xh_ptr, *Bh_ptr, *Bl_ptr, *Ch_ptr, *Cl_ptr;
    cudaGetSymbolAddress((void**)&uB_ptr, g_uB);
    cudaGetSymbolAddress((void**)&uh_ptr, g_uh);
    cudaGetSymbolAddress((void**)&xh_ptr, g_xh);
    cudaGetSymbolAddress((void**)&Bh_ptr, g_Bh);
    cudaGetSymbolAddress((void**)&Bl_ptr, g_Bl);
    cudaGetSymbolAddress((void**)&Ch_ptr, g_Ch);
    cudaGetSymbolAddress((void**)&Cl_ptr, g_Cl);

    cudaFuncSetAttribute(gemm_hmma_h, cudaFuncAttributeMaxDynamicSharedMemorySize, GEMM_SMEM);

    const int M = BATCH * LEN;   // 32768

    // Pre-passes: u -> fp16; split weights once
    {
        int n = M * IND;
        cvt_half_kernel<<<n / (256 * 8), 256>>>(u, uh_ptr, n);
        split_kernel<<<(IND * ST) / (256 * 8), 256>>>(B, Bh_ptr, Bl_ptr, IND * ST);
        split_kernel<<<(ST * OUTD) / (256 * 8), 256>>>(C, Ch_ptr, Cl_ptr, ST * OUTD);
    }

    // GEMM1: uB = uh @ (Bh+Bl)   [32768,512] @ [512,256]
    {
        dim3 grid(ST / BN, M / BM);
        gemm_hmma_h<<<grid, 256, GEMM_SMEM>>>(uh_ptr, Bh_ptr, Bl_ptr, uB_ptr, M, ST, IND);
    }

    // Scan
    scan1_kernel<<<BATCH * NCH, ST / 2>>>(A);
    scan2_kernel<<<BATCH, ST / 2>>>(A, x0);
    scan3_kernel<<<BATCH * NCH, ST / 2>>>(A, xlast);

    // GEMM2: y = xh @ (Ch+Cl)    [32768,256] @ [256,512]
    {
        dim3 grid(OUTD / BN, M / BM);
        gemm_hmma_h<<<grid, 256, GEMM_SMEM>>>(xh_ptr, Ch_ptr, Cl_ptr, y, M, OUTD, ST);
    }
}

// round 11
// speedup vs baseline: 1.2057x; 1.1225x over previous
#include <cuda_runtime.h>
#include <cuda_fp16.h>
#include <cstdint>
#include <cstddef>

// Problem constants
#define BATCH 8
#define LEN   4096
#define IND   512
#define ST    256
#define OUTD  512

#define CHUNK 32
#define NCH   (LEN / CHUNK)   // 128

// Scratch in device globals (no allocation allowed)
__device__ float g_uB[(size_t)BATCH * LEN * ST];      // 32 MB (fp32 scan input)
__device__ half  g_uh[(size_t)BATCH * LEN * IND];     // 32 MB (u as fp16)
__device__ half  g_xh[(size_t)BATCH * LEN * ST];      // 16 MB (x as fp16)
__device__ float g_carry[BATCH * NCH * ST];
__device__ float g_init [BATCH * NCH * ST];
__device__ half  g_Bh[IND * ST], g_Bl[IND * ST];      // B split
__device__ half  g_Ch[ST * OUTD], g_Cl[ST * OUTD];    // C split

// ---------------------------------------------------------------------------
// HMMA asymmetric-split GEMM, all-half inputs:
//   Cm[M,N](fp32) = Ah[M,K] @ (Bh + Bl)[K,N]
// CTA tile 128x128x32, 8 warps as 2m x 4n, warp tile 64x32 (min LDSM
// bytes/MMA since B counts twice). cp.async double-buffered staging,
// __launch_bounds__(256,2) to pin 2 CTAs/SM.
// ---------------------------------------------------------------------------
#define BM 128
#define BN 128
#define BKK 32
#define ALD 40    // A smem leading dim in halves (pad 32->40)
#define BLD 136   // B smem leading dim in halves (pad 128->136)
#define A_SZ (BM * ALD)                 // 5120 halves
#define B_SZ (BKK * BLD)                // 4352 halves
#define A_B  (A_SZ * 2)                 // 10240 bytes
#define B_B  (B_SZ * 2)                 // 8704 bytes
#define STAGE_B (A_B + 2 * B_B)         // 27648 bytes
#define GEMM_SMEM (2 * STAGE_B)         // 55296 bytes

__device__ __forceinline__ uint32_t smem_u32(const void* p) {
    uint32_t a;
    asm("{ .reg .u64 t; cvta.to.shared.u64 t, %1; cvt.u32.u64 %0, t; }"
        : "=r"(a) : "l"(p));
    return a;
}

#define CP16(saddr, gptr) \
    asm volatile("cp.async.cg.shared.global [%0], [%1], 16;" \
        :: "r"(saddr), "l"(gptr))
#define CP_COMMIT() asm volatile("cp.async.commit_group;" ::: "memory")
#define CP_WAIT(n)  asm volatile("cp.async.wait_group %0;" :: "n"(n) : "memory")

#define LDSM_X4(r, addr) \
    asm volatile("ldmatrix.sync.aligned.m8n8.x4.shared.b16 {%0,%1,%2,%3}, [%4];" \
        : "=r"((r)[0]), "=r"((r)[1]), "=r"((r)[2]), "=r"((r)[3]) : "r"(addr))

#define LDSM_X4T(r, addr) \
    asm volatile("ldmatrix.sync.aligned.m8n8.x4.trans.shared.b16 {%0,%1,%2,%3}, [%4];" \
        : "=r"((r)[0]), "=r"((r)[1]), "=r"((r)[2]), "=r"((r)[3]) : "r"(addr))

#define MMA16816(d, a, b0, b1) \
    asm volatile("mma.sync.aligned.m16n8k16.row.col.f32.f16.f16.f32 " \
        "{%0,%1,%2,%3}, {%4,%5,%6,%7}, {%8,%9}, {%0,%1,%2,%3};" \
        : "+f"((d)[0]), "+f"((d)[1]), "+f"((d)[2]), "+f"((d)[3]) \
        : "r"((a)[0]), "r"((a)[1]), "r"((a)[2]), "r"((a)[3]), \
          "r"(b0), "r"(b1))

__global__ __launch_bounds__(256, 2)
void gemm_hmma_h(const half* __restrict__ Ag_, const half* __restrict__ Bhg,
                 const half* __restrict__ Blg, float* __restrict__ Cm,
                 int M, int N, int K) {
    extern __shared__ half sm[];
    const uint32_t sbase = smem_u32(sm);
    const int tid = threadIdx.x;
    const int lane = tid & 31, wid = tid >> 5;
    const int warp_m = wid >> 2;  // 0..1  -> 64 rows each
    const int warp_n = wid & 3;   // 0..3  -> 32 cols each
    const int rowBase = blockIdx.y * BM;
    const int colBase = blockIdx.x * BN;

    // Staging maps: per thread 16 halves (2 x cp.async 16B) per tile
    const int ar = tid >> 1, ac = (tid & 1) * 16;   // A: 128 rows x 32 cols
    const int br = tid >> 3, bc = (tid & 7) * 16;   // B: 32 rows x 128 cols

    const half* Ag  = Ag_ + (size_t)(rowBase + ar) * K + ac;
    const half* Bg0 = Bhg + (size_t)br * N + colBase + bc;
    const half* Bg1 = Blg + (size_t)br * N + colBase + bc;

    const uint32_t sAoff = (uint32_t)(ar * ALD + ac) * 2;
    const uint32_t sBoff = (uint32_t)A_B + (uint32_t)(br * BLD + bc) * 2;

    float acc[4][4][4] = {};

    // prologue: stage 0
    {
        uint32_t base = sbase;
        CP16(base + sAoff,            Ag);
        CP16(base + sAoff + 16,       Ag + 8);
        CP16(base + sBoff,            Bg0);
        CP16(base + sBoff + 16,       Bg0 + 8);
        CP16(base + sBoff + B_B,      Bg1);
        CP16(base + sBoff + B_B + 16, Bg1 + 8);
    }
    CP_COMMIT();

    const int nst = K / BKK;
    for (int s = 0; s < nst; s++) {
        const int cur = s & 1;
        if (s + 1 < nst) {
            const int k0 = (s + 1) * BKK;
            uint32_t base = sbase + (cur ^ 1) * STAGE_B;
            const half* a  = Ag + k0;
            const half* b0 = Bg0 + (size_t)k0 * N;
            const half* b1 = Bg1 + (size_t)k0 * N;
            CP16(base + sAoff,            a);
            CP16(base + sAoff + 16,       a + 8);
            CP16(base + sBoff,            b0);
            CP16(base + sBoff + 16,       b0 + 8);
            CP16(base + sBoff + B_B,      b1);
            CP16(base + sBoff + B_B + 16, b1 + 8);
            CP_COMMIT();
            CP_WAIT(1);
        } else {
            CP_WAIT(0);
        }
        __syncthreads();

        // compute on stage cur
        {
            const uint32_t base = sbase + cur * STAGE_B;
            #pragma unroll
            for (int k16 = 0; k16 < 2; k16++) {
                uint32_t ah[4][4], bh[2][4], bl[2][4];
                const int arow = warp_m * 64 + (lane & 15);
                const int acol = k16 * 16 + (lane >> 4) * 8;
                #pragma unroll
                for (int mi = 0; mi < 4; mi++)
                    LDSM_X4(ah[mi], base + (uint32_t)((arow + mi * 16) * ALD + acol) * 2);
                const int brow = k16 * 16 + (lane & 15);
                const int bcol = warp_n * 32 + (lane >> 4) * 8;
                #pragma unroll
                for (int ni = 0; ni < 2; ni++) {
                    uint32_t boff = (uint32_t)A_B + (uint32_t)(brow * BLD + bcol + ni * 16) * 2;
                    LDSM_X4T(bh[ni], base + boff);
                    LDSM_X4T(bl[ni], base + boff + (uint32_t)B_B);
                }
                #pragma unroll
                for (int mi = 0; mi < 4; mi++)
                    #pragma unroll
                    for (int nj = 0; nj < 4; nj++) {
                        const int ni = nj >> 1, ro = (nj & 1) * 2;
                        MMA16816(acc[mi][nj], ah[mi], bh[ni][ro], bh[ni][ro + 1]);
                        MMA16816(acc[mi][nj], ah[mi], bl[ni][ro], bl[ni][ro + 1]);
                    }
            }
        }
        __syncthreads();
    }

    // Epilogue
    const int g = lane >> 2;
    const int cc = (lane & 3) * 2;
    #pragma unroll
    for (int mi = 0; mi < 4; mi++) {
        const int r0 = rowBase + warp_m * 64 + mi * 16 + g;
        #pragma unroll
        for (int nj = 0; nj < 4; nj++) {
            const int c0 = colBase + warp_n * 32 + nj * 8 + cc;
            *(float2*)&Cm[(size_t)r0 * N + c0]       = make_float2(acc[mi][nj][0], acc[mi][nj][1]);
            *(float2*)&Cm[(size_t)(r0 + 8) * N + c0] = make_float2(acc[mi][nj][2], acc[mi][nj][3]);
        }
    }
}

// ---------------------------------------------------------------------------
// fp32 -> fp16 bulk convert (8 elems/thread)
// ---------------------------------------------------------------------------
__global__ __launch_bounds__(256)
void cvt_half_kernel(const float* __restrict__ in, half* __restrict__ out, int n) {
    int i = (blockIdx.x * 256 + threadIdx.x) * 8;
    if (i >= n) return;
    float4 v0 = *(const float4*)(in + i);
    float4 v1 = *(const float4*)(in + i + 4);
    half2 h[4];
    h[0] = __floats2half2_rn(v0.x, v0.y);
    h[1] = __floats2half2_rn(v0.z, v0.w);
    h[2] = __floats2half2_rn(v1.x, v1.y);
    h[3] = __floats2half2_rn(v1.z, v1.w);
    *(uint4*)(out + i) = *(uint4*)h;
}

// ---------------------------------------------------------------------------
// fp32 -> (hi, lo) fp16 split (8 elems/thread) — for weights
// ---------------------------------------------------------------------------
__global__ __launch_bounds__(256)
void split_kernel(const float* __restrict__ in, half* __restrict__ hi,
                  half* __restrict__ lo, int n) {
    int i = (blockIdx.x * 256 + threadIdx.x) * 8;
    if (i >= n) return;
    float v[8];
    *(float4*)&v[0] = *(const float4*)(in + i);
    *(float4*)&v[4] = *(const float4*)(in + i + 4);
    half h[8], l[8];
    #pragma unroll
    for (int j = 0; j < 8; j++) {
        h[j] = __float2half_rn(v[j]);
        l[j] = __float2half_rn(v[j] - __half2float(h[j]));
    }
    *(uint4*)(hi + i) = *(uint4*)h;
    *(uint4*)(lo + i) = *(uint4*)l;
}

// ---------------------------------------------------------------------------
// Scan pass 1: per-chunk carry with zero initial state.
// ---------------------------------------------------------------------------
__global__ __launch_bounds__(ST / 2)
void scan1_kernel(const float* __restrict__ A) {
    const int n2 = threadIdx.x;
    const int c = blockIdx.x % NCH;
    const int b = blockIdx.x / NCH;
    const float2 a = ((const float2*)A)[n2];
    const float2* p = (const float2*)(g_uB + ((size_t)(b * LEN + c * CHUNK)) * ST) + n2;
    float2 s = make_float2(0.0f, 0.0f);
    #pragma unroll
    for (int t = 0; t < CHUNK; t++) {
        float2 v = p[(size_t)t * (ST / 2)];
        s.x = fmaf(a.x, s.x, v.x);
        s.y = fmaf(a.y, s.y, v.y);
    }
    ((float2*)g_carry)[(b * NCH + c) * (ST / 2) + n2] = s;
}

// ---------------------------------------------------------------------------
// Scan pass 2: inter-chunk exclusive prefix combine.
// ---------------------------------------------------------------------------
__global__ __launch_bounds__(ST / 2)
void scan2_kernel(const float* __restrict__ A, const float* __restrict__ x0) {
    const int n2 = threadIdx.x;
    const int b = blockIdx.x;
    const float2 a = ((const float2*)A)[n2];
    float2 aL = a;
    #pragma unroll
    for (int i = 0; i < 5; i++) { aL.x *= aL.x; aL.y *= aL.y; }   // a^32
    float2 s = ((const float2*)x0)[b * (ST / 2) + n2];
    #pragma unroll
    for (int c = 0; c < NCH; c++) {
        ((float2*)g_init)[(b * NCH + c) * (ST / 2) + n2] = s;
        float2 cv = ((const float2*)g_carry)[(b * NCH + c) * (ST / 2) + n2];
        s.x = fmaf(aL.x, s.x, cv.x);
        s.y = fmaf(aL.y, s.y, cv.y);
    }
}

// ---------------------------------------------------------------------------
// Scan pass 3: rescan per chunk from true init, write x as fp16 (GEMM2 input).
// ---------------------------------------------------------------------------
__global__ __launch_bounds__(ST / 2)
void scan3_kernel(const float* __restrict__ A, float* __restrict__ xlast) {
    const int n2 = threadIdx.x;
    const int c = blockIdx.x % NCH;
    const int b = blockIdx.x / NCH;
    const float2 a = ((const float2*)A)[n2];
    float2 s = ((const float2*)g_init)[(b * NCH + c) * (ST / 2) + n2];
    const size_t base = ((size_t)(b * LEN + c * CHUNK)) * (ST / 2) + n2;
    const float2* pin = (const float2*)g_uB;
    half2* pout = (half2*)g_xh;
    #pragma unroll
    for (int t = 0; t < CHUNK; t++) {
        float2 v = pin[base + (size_t)t * (ST / 2)];
        s.x = fmaf(a.x, s.x, v.x);
        s.y = fmaf(a.y, s.y, v.y);
        pout[base + (size_t)t * (ST / 2)] = __floats2half2_rn(s.x, s.y);
    }
    if (c == NCH - 1) {
        ((float2*)xlast)[b * (ST / 2) + n2] = s;
    }
}

// ---------------------------------------------------------------------------
// kernel_launch
// Inputs: u [8,4096,512], x0 [8,256], A [256], B [512,256], C [256,512]
// Output: y [8,4096,512] flattened, then x_last [8,256].
// ---------------------------------------------------------------------------
extern "C" void kernel_launch(void* const* d_in, const int* in_sizes, int n_in,
                              void* d_out, int out_size) {
    const float* u  = (const float*)d_in[0];
    const float* x0 = (const float*)d_in[1];
    const float* A  = (const float*)d_in[2];
    const float* B  = (const float*)d_in[3];
    const float* C  = (const float*)d_in[4];

    float* y = (float*)d_out;
    float* xlast = y + (size_t)BATCH * LEN * OUTD;

    float *uB_ptr;
    half *uh_ptr, *xh_ptr, *Bh_ptr, *Bl_ptr, *Ch_ptr, *Cl_ptr;
    cudaGetSymbolAddress((void**)&uB_ptr, g_uB);
    cudaGetSymbolAddress((void**)&uh_ptr, g_uh);
    cudaGetSymbolAddress((void**)&xh_ptr, g_xh);
    cudaGetSymbolAddress((void**)&Bh_ptr, g_Bh);
    cudaGetSymbolAddress((void**)&Bl_ptr, g_Bl);
    cudaGetSymbolAddress((void**)&Ch_ptr, g_Ch);
    cudaGetSymbolAddress((void**)&Cl_ptr, g_Cl);

    cudaFuncSetAttribute(gemm_hmma_h, cudaFuncAttributeMaxDynamicSharedMemorySize, GEMM_SMEM);

    const int M = BATCH * LEN;   // 32768

    // Pre-passes: u -> fp16; split weights once
    {
        int n = M * IND;
        cvt_half_kernel<<<n / (256 * 8), 256>>>(u, uh_ptr, n);
        split_kernel<<<(IND * ST) / (256 * 8), 256>>>(B, Bh_ptr, Bl_ptr, IND * ST);
        split_kernel<<<(ST * OUTD) / (256 * 8), 256>>>(C, Ch_ptr, Cl_ptr, ST * OUTD);
    }

    // GEMM1: uB = uh @ (Bh+Bl)   [32768,512] @ [512,256]
    {
        dim3 grid(ST / BN, M / BM);
        gemm_hmma_h<<<grid, 256, GEMM_SMEM>>>(uh_ptr, Bh_ptr, Bl_ptr, uB_ptr, M, ST, IND);
    }

    // Scan
    scan1_kernel<<<BATCH * NCH, ST / 2>>>(A);
    scan2_kernel<<<BATCH, ST / 2>>>(A, x0);
    scan3_kernel<<<BATCH * NCH, ST / 2>>>(A, xlast);

    // GEMM2: y = xh @ (Ch+Cl)    [32768,256] @ [256,512]
    {
        dim3 grid(OUTD / BN, M / BM);
        gemm_hmma_h<<<grid, 256, GEMM_SMEM>>>(xh_ptr, Ch_ptr, Cl_ptr, y, M, OUTD, ST);
    }
}

// round 12
// speedup vs baseline: 1.2439x; 1.0317x over previous
#include <cuda_runtime.h>
#include <cuda_fp16.h>
#include <cstdint>
#include <cstddef>

// Problem constants
#define BATCH 8
#define LEN   4096
#define IND   512
#define ST    256
#define OUTD  512

#define CHUNK 32
#define NCH   (LEN / CHUNK)   // 128

// Scratch in device globals (no allocation allowed)
__device__ float g_uB[(size_t)BATCH * LEN * ST];      // 32 MB (fp32 scan input)
__device__ half  g_uh[(size_t)BATCH * LEN * IND];     // 32 MB (u as fp16)
__device__ half  g_xh[(size_t)BATCH * LEN * ST];      // 16 MB (x as fp16)
__device__ float g_carry[BATCH * NCH * ST];
__device__ float g_init [BATCH * NCH * ST];
__device__ half  g_Bh[IND * ST], g_Bl[IND * ST];      // B split
__device__ half  g_Ch[ST * OUTD], g_Cl[ST * OUTD];    // C split

// ---------------------------------------------------------------------------
// HMMA asymmetric-split GEMM, all-half inputs:
//   Cm[M,N](fp32) = Ah[M,K] @ (Bh + Bl)[K,N]
// CTA tile 128x128x32, 8 warps as 2m x 4n, warp tile 64x32.
// 3-stage cp.async pipeline, ONE __syncthreads per K-stage.
// ---------------------------------------------------------------------------
#define BM 128
#define BN 128
#define BKK 32
#define ALD 40    // A smem leading dim in halves (pad 32->40)
#define BLD 136   // B smem leading dim in halves (pad 128->136)
#define A_SZ (BM * ALD)                 // 5120 halves
#define B_SZ (BKK * BLD)                // 4352 halves
#define A_B  (A_SZ * 2)                 // 10240 bytes
#define B_B  (B_SZ * 2)                 // 8704 bytes
#define STAGE_B (A_B + 2 * B_B)         // 27648 bytes
#define NSTAGE 3
#define GEMM_SMEM (NSTAGE * STAGE_B)    // 82944 bytes

__device__ __forceinline__ uint32_t smem_u32(const void* p) {
    uint32_t a;
    asm("{ .reg .u64 t; cvta.to.shared.u64 t, %1; cvt.u32.u64 %0, t; }"
        : "=r"(a) : "l"(p));
    return a;
}

#define CP16(saddr, gptr) \
    asm volatile("cp.async.cg.shared.global [%0], [%1], 16;" \
        :: "r"(saddr), "l"(gptr))
#define CP_COMMIT() asm volatile("cp.async.commit_group;" ::: "memory")
#define CP_WAIT(n)  asm volatile("cp.async.wait_group %0;" :: "n"(n) : "memory")

#define LDSM_X4(r, addr) \
    asm volatile("ldmatrix.sync.aligned.m8n8.x4.shared.b16 {%0,%1,%2,%3}, [%4];" \
        : "=r"((r)[0]), "=r"((r)[1]), "=r"((r)[2]), "=r"((r)[3]) : "r"(addr))

#define LDSM_X4T(r, addr) \
    asm volatile("ldmatrix.sync.aligned.m8n8.x4.trans.shared.b16 {%0,%1,%2,%3}, [%4];" \
        : "=r"((r)[0]), "=r"((r)[1]), "=r"((r)[2]), "=r"((r)[3]) : "r"(addr))

#define MMA16816(d, a, b0, b1) \
    asm volatile("mma.sync.aligned.m16n8k16.row.col.f32.f16.f16.f32 " \
        "{%0,%1,%2,%3}, {%4,%5,%6,%7}, {%8,%9}, {%0,%1,%2,%3};" \
        : "+f"((d)[0]), "+f"((d)[1]), "+f"((d)[2]), "+f"((d)[3]) \
        : "r"((a)[0]), "r"((a)[1]), "r"((a)[2]), "r"((a)[3]), \
          "r"(b0), "r"(b1))

__global__ __launch_bounds__(256, 2)
void gemm_hmma_h(const half* __restrict__ Ag_, const half* __restrict__ Bhg,
                 const half* __restrict__ Blg, float* __restrict__ Cm,
                 int M, int N, int K) {
    extern __shared__ half sm[];
    const uint32_t sbase = smem_u32(sm);
    const int tid = threadIdx.x;
    const int lane = tid & 31, wid = tid >> 5;
    const int warp_m = wid >> 2;  // 0..1  -> 64 rows each
    const int warp_n = wid & 3;   // 0..3  -> 32 cols each
    const int rowBase = blockIdx.y * BM;
    const int colBase = blockIdx.x * BN;

    // Staging maps: per thread 16 halves (2 x cp.async 16B) per tile
    const int ar = tid >> 1, ac = (tid & 1) * 16;   // A: 128 rows x 32 cols
    const int br = tid >> 3, bc = (tid & 7) * 16;   // B: 32 rows x 128 cols

    const half* Ag  = Ag_ + (size_t)(rowBase + ar) * K + ac;
    const half* Bg0 = Bhg + (size_t)br * N + colBase + bc;
    const half* Bg1 = Blg + (size_t)br * N + colBase + bc;

    const uint32_t sAoff = (uint32_t)(ar * ALD + ac) * 2;
    const uint32_t sBoff = (uint32_t)A_B + (uint32_t)(br * BLD + bc) * 2;

    float acc[4][4][4] = {};

    const int nst = K / BKK;

    // prologue: stages 0 and 1
    #pragma unroll
    for (int p = 0; p < 2; p++) {
        uint32_t base = sbase + p * STAGE_B;
        const int k0 = p * BKK;
        const half* a  = Ag + k0;
        const half* b0 = Bg0 + (size_t)k0 * N;
        const half* b1 = Bg1 + (size_t)k0 * N;
        CP16(base + sAoff,            a);
        CP16(base + sAoff + 16,       a + 8);
        CP16(base + sBoff,            b0);
        CP16(base + sBoff + 16,       b0 + 8);
        CP16(base + sBoff + B_B,      b1);
        CP16(base + sBoff + B_B + 16, b1 + 8);
        CP_COMMIT();
    }

    int cur = 0;        // s % 3
    int nxt2 = 2;       // (s+2) % 3
    for (int s = 0; s < nst; s++) {
        CP_WAIT(1);         // stage s landed (FIFO completion)
        __syncthreads();    // everyone done with stage s-1 compute, sees stage s

        if (s + 2 < nst) {
            const int k0 = (s + 2) * BKK;
            uint32_t base = sbase + nxt2 * STAGE_B;
            const half* a  = Ag + k0;
            const half* b0 = Bg0 + (size_t)k0 * N;
            const half* b1 = Bg1 + (size_t)k0 * N;
            CP16(base + sAoff,            a);
            CP16(base + sAoff + 16,       a + 8);
            CP16(base + sBoff,            b0);
            CP16(base + sBoff + 16,       b0 + 8);
            CP16(base + sBoff + B_B,      b1);
            CP16(base + sBoff + B_B + 16, b1 + 8);
        }
        CP_COMMIT();        // always commit to keep group counting uniform

        // compute on stage cur
        {
            const uint32_t base = sbase + cur * STAGE_B;
            #pragma unroll
            for (int k16 = 0; k16 < 2; k16++) {
                uint32_t ah[4][4], bh[2][4], bl[2][4];
                const int arow = warp_m * 64 + (lane & 15);
                const int acol = k16 * 16 + (lane >> 4) * 8;
                #pragma unroll
                for (int mi = 0; mi < 4; mi++)
                    LDSM_X4(ah[mi], base + (uint32_t)((arow + mi * 16) * ALD + acol) * 2);
                const int brow = k16 * 16 + (lane & 15);
                const int bcol = warp_n * 32 + (lane >> 4) * 8;
                #pragma unroll
                for (int ni = 0; ni < 2; ni++) {
                    uint32_t boff = (uint32_t)A_B + (uint32_t)(brow * BLD + bcol + ni * 16) * 2;
                    LDSM_X4T(bh[ni], base + boff);
                    LDSM_X4T(bl[ni], base + boff + (uint32_t)B_B);
                }
                #pragma unroll
                for (int mi = 0; mi < 4; mi++)
                    #pragma unroll
                    for (int nj = 0; nj < 4; nj++) {
                        const int ni = nj >> 1, ro = (nj & 1) * 2;
                        MMA16816(acc[mi][nj], ah[mi], bh[ni][ro], bh[ni][ro + 1]);
                        MMA16816(acc[mi][nj], ah[mi], bl[ni][ro], bl[ni][ro + 1]);
                    }
            }
        }

        cur = (cur == 2) ? 0 : cur + 1;
        nxt2 = (nxt2 == 2) ? 0 : nxt2 + 1;
    }

    // Epilogue
    const int g = lane >> 2;
    const int cc = (lane & 3) * 2;
    #pragma unroll
    for (int mi = 0; mi < 4; mi++) {
        const int r0 = rowBase + warp_m * 64 + mi * 16 + g;
        #pragma unroll
        for (int nj = 0; nj < 4; nj++) {
            const int c0 = colBase + warp_n * 32 + nj * 8 + cc;
            *(float2*)&Cm[(size_t)r0 * N + c0]       = make_float2(acc[mi][nj][0], acc[mi][nj][1]);
            *(float2*)&Cm[(size_t)(r0 + 8) * N + c0] = make_float2(acc[mi][nj][2], acc[mi][nj][3]);
        }
    }
}

// ---------------------------------------------------------------------------
// fp32 -> fp16 bulk convert (8 elems/thread)
// ---------------------------------------------------------------------------
__global__ __launch_bounds__(256)
void cvt_half_kernel(const float* __restrict__ in, half* __restrict__ out, int n) {
    int i = (blockIdx.x * 256 + threadIdx.x) * 8;
    if (i >= n) return;
    float4 v0 = *(const float4*)(in + i);
    float4 v1 = *(const float4*)(in + i + 4);
    half2 h[4];
    h[0] = __floats2half2_rn(v0.x, v0.y);
    h[1] = __floats2half2_rn(v0.z, v0.w);
    h[2] = __floats2half2_rn(v1.x, v1.y);
    h[3] = __floats2half2_rn(v1.z, v1.w);
    *(uint4*)(out + i) = *(uint4*)h;
}

// ---------------------------------------------------------------------------
// fp32 -> (hi, lo) fp16 split (8 elems/thread) — for weights
// ---------------------------------------------------------------------------
__global__ __launch_bounds__(256)
void split_kernel(const float* __restrict__ in, half* __restrict__ hi,
                  half* __restrict__ lo, int n) {
    int i = (blockIdx.x * 256 + threadIdx.x) * 8;
    if (i >= n) return;
    float v[8];
    *(float4*)&v[0] = *(const float4*)(in + i);
    *(float4*)&v[4] = *(const float4*)(in + i + 4);
    half h[8], l[8];
    #pragma unroll
    for (int j = 0; j < 8; j++) {
        h[j] = __float2half_rn(v[j]);
        l[j] = __float2half_rn(v[j] - __half2float(h[j]));
    }
    *(uint4*)(hi + i) = *(uint4*)h;
    *(uint4*)(lo + i) = *(uint4*)l;
}

// ---------------------------------------------------------------------------
// Scan pass 1: per-chunk carry with zero initial state.
// ---------------------------------------------------------------------------
__global__ __launch_bounds__(ST / 2)
void scan1_kernel(const float* __restrict__ A) {
    const int n2 = threadIdx.x;
    const int c = blockIdx.x % NCH;
    const int b = blockIdx.x / NCH;
    const float2 a = ((const float2*)A)[n2];
    const float2* p = (const float2*)(g_uB + ((size_t)(b * LEN + c * CHUNK)) * ST) + n2;
    float2 s = make_float2(0.0f, 0.0f);
    #pragma unroll
    for (int t = 0; t < CHUNK; t++) {
        float2 v = p[(size_t)t * (ST / 2)];
        s.x = fmaf(a.x, s.x, v.x);
        s.y = fmaf(a.y, s.y, v.y);
    }
    ((float2*)g_carry)[(b * NCH + c) * (ST / 2) + n2] = s;
}

// ---------------------------------------------------------------------------
// Scan pass 2: inter-chunk exclusive prefix combine.
// ---------------------------------------------------------------------------
__global__ __launch_bounds__(ST / 2)
void scan2_kernel(const float* __restrict__ A, const float* __restrict__ x0) {
    const int n2 = threadIdx.x;
    const int b = blockIdx.x;
    const float2 a = ((const float2*)A)[n2];
    float2 aL = a;
    #pragma unroll
    for (int i = 0; i < 5; i++) { aL.x *= aL.x; aL.y *= aL.y; }   // a^32
    float2 s = ((const float2*)x0)[b * (ST / 2) + n2];
    #pragma unroll
    for (int c = 0; c < NCH; c++) {
        ((float2*)g_init)[(b * NCH + c) * (ST / 2) + n2] = s;
        float2 cv = ((const float2*)g_carry)[(b * NCH + c) * (ST / 2) + n2];
        s.x = fmaf(aL.x, s.x, cv.x);
        s.y = fmaf(aL.y, s.y, cv.y);
    }
}

// ---------------------------------------------------------------------------
// Scan pass 3: rescan per chunk from true init, write x as fp16 (GEMM2 input).
// ---------------------------------------------------------------------------
__global__ __launch_bounds__(ST / 2)
void scan3_kernel(const float* __restrict__ A, float* __restrict__ xlast) {
    const int n2 = threadIdx.x;
    const int c = blockIdx.x % NCH;
    const int b = blockIdx.x / NCH;
    const float2 a = ((const float2*)A)[n2];
    float2 s = ((const float2*)g_init)[(b * NCH + c) * (ST / 2) + n2];
    const size_t base = ((size_t)(b * LEN + c * CHUNK)) * (ST / 2) + n2;
    const float2* pin = (const float2*)g_uB;
    half2* pout = (half2*)g_xh;
    #pragma unroll
    for (int t = 0; t < CHUNK; t++) {
        float2 v = pin[base + (size_t)t * (ST / 2)];
        s.x = fmaf(a.x, s.x, v.x);
        s.y = fmaf(a.y, s.y, v.y);
        pout[base + (size_t)t * (ST / 2)] = __floats2half2_rn(s.x, s.y);
    }
    if (c == NCH - 1) {
        ((float2*)xlast)[b * (ST / 2) + n2] = s;
    }
}

// ---------------------------------------------------------------------------
// kernel_launch
// Inputs: u [8,4096,512], x0 [8,256], A [256], B [512,256], C [256,512]
// Output: y [8,4096,512] flattened, then x_last [8,256].
// ---------------------------------------------------------------------------
extern "C" void kernel_launch(void* const* d_in, const int* in_sizes, int n_in,
                              void* d_out, int out_size) {
    const float* u  = (const float*)d_in[0];
    const float* x0 = (const float*)d_in[1];
    const float* A  = (const float*)d_in[2];
    const float* B  = (const float*)d_in[3];
    const float* C  = (const float*)d_in[4];

    float* y = (float*)d_out;
    float* xlast = y + (size_t)BATCH * LEN * OUTD;

    float *uB_ptr;
    half *uh_ptr, *xh_ptr, *Bh_ptr, *Bl_ptr, *Ch_ptr, *Cl_ptr;
    cudaGetSymbolAddress((void**)&uB_ptr, g_uB);
    cudaGetSymbolAddress((void**)&uh_ptr, g_uh);
    cudaGetSymbolAddress((void**)&xh_ptr, g_xh);
    cudaGetSymbolAddress((void**)&Bh_ptr, g_Bh);
    cudaGetSymbolAddress((void**)&Bl_ptr, g_Bl);
    cudaGetSymbolAddress((void**)&Ch_ptr, g_Ch);
    cudaGetSymbolAddress((void**)&Cl_ptr, g_Cl);

    cudaFuncSetAttribute(gemm_hmma_h, cudaFuncAttributeMaxDynamicSharedMemorySize, GEMM_SMEM);

    const int M = BATCH * LEN;   // 32768

    // Pre-passes: u -> fp16; split weights once
    {
        int n = M * IND;
        cvt_half_kernel<<<n / (256 * 8), 256>>>(u, uh_ptr, n);
        split_kernel<<<(IND * ST) / (256 * 8), 256>>>(B, Bh_ptr, Bl_ptr, IND * ST);
        split_kernel<<<(ST * OUTD) / (256 * 8), 256>>>(C, Ch_ptr, Cl_ptr, ST * OUTD);
    }

    // GEMM1: uB = uh @ (Bh+Bl)   [32768,512] @ [512,256]
    {
        dim3 grid(ST / BN, M / BM);
        gemm_hmma_h<<<grid, 256, GEMM_SMEM>>>(uh_ptr, Bh_ptr, Bl_ptr, uB_ptr, M, ST, IND);
    }

    // Scan
    scan1_kernel<<<BATCH * NCH, ST / 2>>>(A);
    scan2_kernel<<<BATCH, ST / 2>>>(A, x0);
    scan3_kernel<<<BATCH * NCH, ST / 2>>>(A, xlast);

    // GEMM2: y = xh @ (Ch+Cl)    [32768,256] @ [256,512]
    {
        dim3 grid(OUTD / BN, M / BM);
        gemm_hmma_h<<<grid, 256, GEMM_SMEM>>>(xh_ptr, Ch_ptr, Cl_ptr, y, M, OUTD, ST);
    }
}

// round 13
// speedup vs baseline: 1.6127x; 1.2965x over previous
#include <cuda_runtime.h>
#include <cuda_fp16.h>
#include <cstdint>
#include <cstddef>

// Problem constants
#define BATCH 8
#define LEN   4096
#define IND   512
#define ST    256
#define OUTD  512

#define CHUNK 32
#define NCH   (LEN / CHUNK)   // 128

// Scratch in device globals (no allocation allowed)
__device__ float g_uB[(size_t)BATCH * LEN * ST];      // 32 MB (fp32 scan input)
__device__ half  g_uh[(size_t)BATCH * LEN * IND];     // 32 MB (u as fp16)
__device__ half  g_xh[(size_t)BATCH * LEN * ST];      // 16 MB (x as fp16)
__device__ float g_carry[BATCH * NCH * ST];
__device__ float g_init [BATCH * NCH * ST];
__device__ half  g_Bh[IND * ST];                      // B as fp16
__device__ half  g_Ch[ST * OUTD];                     // C as fp16

// ---------------------------------------------------------------------------
// HMMA single-pass fp16 GEMM:  Cm[M,N](fp32) = Ah[M,K](fp16) @ Bh[K,N](fp16)
// CTA tile 128x128x32, 8 warps as 2m x 4n, warp tile 64x32, fp32 accumulate.
// 3-stage cp.async pipeline, one __syncthreads per K-stage.
// ---------------------------------------------------------------------------
#define BM 128
#define BN 128
#define BKK 32
#define ALD 40    // A smem leading dim in halves (pad 32->40)
#define BLD 136   // B smem leading dim in halves (pad 128->136)
#define A_SZ (BM * ALD)                 // 5120 halves
#define B_SZ (BKK * BLD)                // 4352 halves
#define A_B  (A_SZ * 2)                 // 10240 bytes
#define B_B  (B_SZ * 2)                 // 8704 bytes
#define STAGE_B (A_B + B_B)             // 18944 bytes
#define NSTAGE 3
#define GEMM_SMEM (NSTAGE * STAGE_B)    // 56832 bytes

__device__ __forceinline__ uint32_t smem_u32(const void* p) {
    uint32_t a;
    asm("{ .reg .u64 t; cvta.to.shared.u64 t, %1; cvt.u32.u64 %0, t; }"
        : "=r"(a) : "l"(p));
    return a;
}

#define CP16(saddr, gptr) \
    asm volatile("cp.async.cg.shared.global [%0], [%1], 16;" \
        :: "r"(saddr), "l"(gptr))
#define CP_COMMIT() asm volatile("cp.async.commit_group;" ::: "memory")
#define CP_WAIT(n)  asm volatile("cp.async.wait_group %0;" :: "n"(n) : "memory")

#define LDSM_X4(r, addr) \
    asm volatile("ldmatrix.sync.aligned.m8n8.x4.shared.b16 {%0,%1,%2,%3}, [%4];" \
        : "=r"((r)[0]), "=r"((r)[1]), "=r"((r)[2]), "=r"((r)[3]) : "r"(addr))

#define LDSM_X4T(r, addr) \
    asm volatile("ldmatrix.sync.aligned.m8n8.x4.trans.shared.b16 {%0,%1,%2,%3}, [%4];" \
        : "=r"((r)[0]), "=r"((r)[1]), "=r"((r)[2]), "=r"((r)[3]) : "r"(addr))

#define MMA16816(d, a, b0, b1) \
    asm volatile("mma.sync.aligned.m16n8k16.row.col.f32.f16.f16.f32 " \
        "{%0,%1,%2,%3}, {%4,%5,%6,%7}, {%8,%9}, {%0,%1,%2,%3};" \
        : "+f"((d)[0]), "+f"((d)[1]), "+f"((d)[2]), "+f"((d)[3]) \
        : "r"((a)[0]), "r"((a)[1]), "r"((a)[2]), "r"((a)[3]), \
          "r"(b0), "r"(b1))

__global__ __launch_bounds__(256, 2)
void gemm_hmma_h(const half* __restrict__ Ag_, const half* __restrict__ Bhg,
                 float* __restrict__ Cm, int M, int N, int K) {
    extern __shared__ half sm[];
    const uint32_t sbase = smem_u32(sm);
    const int tid = threadIdx.x;
    const int lane = tid & 31, wid = tid >> 5;
    const int warp_m = wid >> 2;  // 0..1  -> 64 rows each
    const int warp_n = wid & 3;   // 0..3  -> 32 cols each
    const int rowBase = blockIdx.y * BM;
    const int colBase = blockIdx.x * BN;

    // Staging maps: per thread 16 halves (2 x cp.async 16B) per tile
    const int ar = tid >> 1, ac = (tid & 1) * 16;   // A: 128 rows x 32 cols
    const int br = tid >> 3, bc = (tid & 7) * 16;   // B: 32 rows x 128 cols

    const half* Ag  = Ag_ + (size_t)(rowBase + ar) * K + ac;
    const half* Bg0 = Bhg + (size_t)br * N + colBase + bc;

    const uint32_t sAoff = (uint32_t)(ar * ALD + ac) * 2;
    const uint32_t sBoff = (uint32_t)A_B + (uint32_t)(br * BLD + bc) * 2;

    float acc[4][4][4] = {};

    const int nst = K / BKK;

    // prologue: stages 0 and 1
    #pragma unroll
    for (int p = 0; p < 2; p++) {
        uint32_t base = sbase + p * STAGE_B;
        const int k0 = p * BKK;
        const half* a  = Ag + k0;
        const half* b0 = Bg0 + (size_t)k0 * N;
        CP16(base + sAoff,      a);
        CP16(base + sAoff + 16, a + 8);
        CP16(base + sBoff,      b0);
        CP16(base + sBoff + 16, b0 + 8);
        CP_COMMIT();
    }

    int cur = 0;        // s % 3
    int nxt2 = 2;       // (s+2) % 3
    for (int s = 0; s < nst; s++) {
        CP_WAIT(1);         // stage s landed (FIFO completion)
        __syncthreads();    // stage s visible; stage s-1 compute done

        if (s + 2 < nst) {
            const int k0 = (s + 2) * BKK;
            uint32_t base = sbase + nxt2 * STAGE_B;
            const half* a  = Ag + k0;
            const half* b0 = Bg0 + (size_t)k0 * N;
            CP16(base + sAoff,      a);
            CP16(base + sAoff + 16, a + 8);
            CP16(base + sBoff,      b0);
            CP16(base + sBoff + 16, b0 + 8);
        }
        CP_COMMIT();        // always commit: uniform group counting

        // compute on stage cur
        {
            const uint32_t base = sbase + cur * STAGE_B;
            #pragma unroll
            for (int k16 = 0; k16 < 2; k16++) {
                uint32_t ah[4][4], bh[2][4];
                const int arow = warp_m * 64 + (lane & 15);
                const int acol = k16 * 16 + (lane >> 4) * 8;
                #pragma unroll
                for (int mi = 0; mi < 4; mi++)
                    LDSM_X4(ah[mi], base + (uint32_t)((arow + mi * 16) * ALD + acol) * 2);
                const int brow = k16 * 16 + (lane & 15);
                const int bcol = warp_n * 32 + (lane >> 4) * 8;
                #pragma unroll
                for (int ni = 0; ni < 2; ni++) {
                    uint32_t boff = (uint32_t)A_B + (uint32_t)(brow * BLD + bcol + ni * 16) * 2;
                    LDSM_X4T(bh[ni], base + boff);
                }
                #pragma unroll
                for (int mi = 0; mi < 4; mi++)
                    #pragma unroll
                    for (int nj = 0; nj < 4; nj++) {
                        const int ni = nj >> 1, ro = (nj & 1) * 2;
                        MMA16816(acc[mi][nj], ah[mi], bh[ni][ro], bh[ni][ro + 1]);
                    }
            }
        }

        cur = (cur == 2) ? 0 : cur + 1;
        nxt2 = (nxt2 == 2) ? 0 : nxt2 + 1;
    }

    // Epilogue
    const int g = lane >> 2;
    const int cc = (lane & 3) * 2;
    #pragma unroll
    for (int mi = 0; mi < 4; mi++) {
        const int r0 = rowBase + warp_m * 64 + mi * 16 + g;
        #pragma unroll
        for (int nj = 0; nj < 4; nj++) {
            const int c0 = colBase + warp_n * 32 + nj * 8 + cc;
            *(float2*)&Cm[(size_t)r0 * N + c0]       = make_float2(acc[mi][nj][0], acc[mi][nj][1]);
            *(float2*)&Cm[(size_t)(r0 + 8) * N + c0] = make_float2(acc[mi][nj][2], acc[mi][nj][3]);
        }
    }
}

// ---------------------------------------------------------------------------
// fp32 -> fp16 bulk convert (8 elems/thread)
// ---------------------------------------------------------------------------
__global__ __launch_bounds__(256)
void cvt_half_kernel(const float* __restrict__ in, half* __restrict__ out, int n) {
    int i = (blockIdx.x * 256 + threadIdx.x) * 8;
    if (i >= n) return;
    float4 v0 = *(const float4*)(in + i);
    float4 v1 = *(const float4*)(in + i + 4);
    half2 h[4];
    h[0] = __floats2half2_rn(v0.x, v0.y);
    h[1] = __floats2half2_rn(v0.z, v0.w);
    h[2] = __floats2half2_rn(v1.x, v1.y);
    h[3] = __floats2half2_rn(v1.z, v1.w);
    *(uint4*)(out + i) = *(uint4*)h;
}

// ---------------------------------------------------------------------------
// Scan pass 1: per-chunk carry with zero initial state.
// ---------------------------------------------------------------------------
__global__ __launch_bounds__(ST / 2)
void scan1_kernel(const float* __restrict__ A) {
    const int n2 = threadIdx.x;
    const int c = blockIdx.x % NCH;
    const int b = blockIdx.x / NCH;
    const float2 a = ((const float2*)A)[n2];
    const float2* p = (const float2*)(g_uB + ((size_t)(b * LEN + c * CHUNK)) * ST) + n2;
    float2 s = make_float2(0.0f, 0.0f);
    #pragma unroll
    for (int t = 0; t < CHUNK; t++) {
        float2 v = p[(size_t)t * (ST / 2)];
        s.x = fmaf(a.x, s.x, v.x);
        s.y = fmaf(a.y, s.y, v.y);
    }
    ((float2*)g_carry)[(b * NCH + c) * (ST / 2) + n2] = s;
}

// ---------------------------------------------------------------------------
// Scan pass 2: inter-chunk exclusive prefix combine.
// ---------------------------------------------------------------------------
__global__ __launch_bounds__(ST / 2)
void scan2_kernel(const float* __restrict__ A, const float* __restrict__ x0) {
    const int n2 = threadIdx.x;
    const int b = blockIdx.x;
    const float2 a = ((const float2*)A)[n2];
    float2 aL = a;
    #pragma unroll
    for (int i = 0; i < 5; i++) { aL.x *= aL.x; aL.y *= aL.y; }   // a^32
    float2 s = ((const float2*)x0)[b * (ST / 2) + n2];
    #pragma unroll
    for (int c = 0; c < NCH; c++) {
        ((float2*)g_init)[(b * NCH + c) * (ST / 2) + n2] = s;
        float2 cv = ((const float2*)g_carry)[(b * NCH + c) * (ST / 2) + n2];
        s.x = fmaf(aL.x, s.x, cv.x);
        s.y = fmaf(aL.y, s.y, cv.y);
    }
}

// ---------------------------------------------------------------------------
// Scan pass 3: rescan per chunk from true init, write x as fp16 (GEMM2 input).
// ---------------------------------------------------------------------------
__global__ __launch_bounds__(ST / 2)
void scan3_kernel(const float* __restrict__ A, float* __restrict__ xlast) {
    const int n2 = threadIdx.x;
    const int c = blockIdx.x % NCH;
    const int b = blockIdx.x / NCH;
    const float2 a = ((const float2*)A)[n2];
    float2 s = ((const float2*)g_init)[(b * NCH + c) * (ST / 2) + n2];
    const size_t base = ((size_t)(b * LEN + c * CHUNK)) * (ST / 2) + n2;
    const float2* pin = (const float2*)g_uB;
    half2* pout = (half2*)g_xh;
    #pragma unroll
    for (int t = 0; t < CHUNK; t++) {
        float2 v = pin[base + (size_t)t * (ST / 2)];
        s.x = fmaf(a.x, s.x, v.x);
        s.y = fmaf(a.y, s.y, v.y);
        pout[base + (size_t)t * (ST / 2)] = __floats2half2_rn(s.x, s.y);
    }
    if (c == NCH - 1) {
        ((float2*)xlast)[b * (ST / 2) + n2] = s;
    }
}

// ---------------------------------------------------------------------------
// kernel_launch
// Inputs: u [8,4096,512], x0 [8,256], A [256], B [512,256], C [256,512]
// Output: y [8,4096,512] flattened, then x_last [8,256].
// ---------------------------------------------------------------------------
extern "C" void kernel_launch(void* const* d_in, const int* in_sizes, int n_in,
                              void* d_out, int out_size) {
    const float* u  = (const float*)d_in[0];
    const float* x0 = (const float*)d_in[1];
    const float* A  = (const float*)d_in[2];
    const float* B  = (const float*)d_in[3];
    const float* C  = (const float*)d_in[4];

    float* y = (float*)d_out;
    float* xlast = y + (size_t)BATCH * LEN * OUTD;

    float *uB_ptr;
    half *uh_ptr, *xh_ptr, *Bh_ptr, *Ch_ptr;
    cudaGetSymbolAddress((void**)&uB_ptr, g_uB);
    cudaGetSymbolAddress((void**)&uh_ptr, g_uh);
    cudaGetSymbolAddress((void**)&xh_ptr, g_xh);
    cudaGetSymbolAddress((void**)&Bh_ptr, g_Bh);
    cudaGetSymbolAddress((void**)&Ch_ptr, g_Ch);

    cudaFuncSetAttribute(gemm_hmma_h, cudaFuncAttributeMaxDynamicSharedMemorySize, GEMM_SMEM);

    const int M = BATCH * LEN;   // 32768

    // Pre-passes: u, B, C -> fp16
    {
        int n = M * IND;
        cvt_half_kernel<<<n / (256 * 8), 256>>>(u, uh_ptr, n);
        cvt_half_kernel<<<(IND * ST) / (256 * 8), 256>>>(B, Bh_ptr, IND * ST);
        cvt_half_kernel<<<(ST * OUTD) / (256 * 8), 256>>>(C, Ch_ptr, ST * OUTD);
    }

    // GEMM1: uB = uh @ Bh   [32768,512] @ [512,256]
    {
        dim3 grid(ST / BN, M / BM);
        gemm_hmma_h<<<grid, 256, GEMM_SMEM>>>(uh_ptr, Bh_ptr, uB_ptr, M, ST, IND);
    }

    // Scan
    scan1_kernel<<<BATCH * NCH, ST / 2>>>(A);
    scan2_kernel<<<BATCH, ST / 2>>>(A, x0);
    scan3_kernel<<<BATCH * NCH, ST / 2>>>(A, xlast);

    // GEMM2: y = xh @ Ch    [32768,256] @ [256,512]
    {
        dim3 grid(OUTD / BN, M / BM);
        gemm_hmma_h<<<grid, 256, GEMM_SMEM>>>(xh_ptr, Ch_ptr, y, M, OUTD, ST);
    }
}

// round 14
// speedup vs baseline: 1.6689x; 1.0348x over previous
#include <cuda_runtime.h>
#include <cuda_fp16.h>
#include <cstdint>
#include <cstddef>

// Problem constants
#define BATCH 8
#define LEN   4096
#define IND   512
#define ST    256
#define OUTD  512

#define CHUNK 32
#define NCH   (LEN / CHUNK)   // 128

// Scratch in device globals (no allocation allowed)
__device__ half  g_uBh[(size_t)BATCH * LEN * ST];     // 16 MB (uB as fp16)
__device__ half  g_uh[(size_t)BATCH * LEN * IND];     // 32 MB (u as fp16)
__device__ half  g_xh[(size_t)BATCH * LEN * ST];      // 16 MB (x as fp16)
__device__ float g_carry[BATCH * NCH * ST];
__device__ float g_init [BATCH * NCH * ST];
__device__ half  g_Bh[IND * ST];                      // B as fp16
__device__ half  g_Ch[ST * OUTD];                     // C as fp16

// ---------------------------------------------------------------------------
// HMMA single-pass fp16 GEMM:  Cm[M,N](OutT) = Ah[M,K](fp16) @ Bh[K,N](fp16)
// CTA tile 128x128x32, 8 warps as 2m x 4n, warp tile 64x32, fp32 accumulate.
// 3-stage cp.async pipeline, one __syncthreads per K-stage.
// ---------------------------------------------------------------------------
#define BM 128
#define BN 128
#define BKK 32
#define ALD 40    // A smem leading dim in halves (pad 32->40)
#define BLD 136   // B smem leading dim in halves (pad 128->136)
#define A_SZ (BM * ALD)                 // 5120 halves
#define B_SZ (BKK * BLD)                // 4352 halves
#define A_B  (A_SZ * 2)                 // 10240 bytes
#define B_B  (B_SZ * 2)                 // 8704 bytes
#define STAGE_B (A_B + B_B)             // 18944 bytes
#define NSTAGE 3
#define GEMM_SMEM (NSTAGE * STAGE_B)    // 56832 bytes

__device__ __forceinline__ uint32_t smem_u32(const void* p) {
    uint32_t a;
    asm("{ .reg .u64 t; cvta.to.shared.u64 t, %1; cvt.u32.u64 %0, t; }"
        : "=r"(a) : "l"(p));
    return a;
}

#define CP16(saddr, gptr) \
    asm volatile("cp.async.cg.shared.global [%0], [%1], 16;" \
        :: "r"(saddr), "l"(gptr))
#define CP_COMMIT() asm volatile("cp.async.commit_group;" ::: "memory")
#define CP_WAIT(n)  asm volatile("cp.async.wait_group %0;" :: "n"(n) : "memory")

#define LDSM_X4(r, addr) \
    asm volatile("ldmatrix.sync.aligned.m8n8.x4.shared.b16 {%0,%1,%2,%3}, [%4];" \
        : "=r"((r)[0]), "=r"((r)[1]), "=r"((r)[2]), "=r"((r)[3]) : "r"(addr))

#define LDSM_X4T(r, addr) \
    asm volatile("ldmatrix.sync.aligned.m8n8.x4.trans.shared.b16 {%0,%1,%2,%3}, [%4];" \
        : "=r"((r)[0]), "=r"((r)[1]), "=r"((r)[2]), "=r"((r)[3]) : "r"(addr))

#define MMA16816(d, a, b0, b1) \
    asm volatile("mma.sync.aligned.m16n8k16.row.col.f32.f16.f16.f32 " \
        "{%0,%1,%2,%3}, {%4,%5,%6,%7}, {%8,%9}, {%0,%1,%2,%3};" \
        : "+f"((d)[0]), "+f"((d)[1]), "+f"((d)[2]), "+f"((d)[3]) \
        : "r"((a)[0]), "r"((a)[1]), "r"((a)[2]), "r"((a)[3]), \
          "r"(b0), "r"(b1))

template <typename OutT>
__global__ __launch_bounds__(256, 2)
void gemm_hmma_h(const half* __restrict__ Ag_, const half* __restrict__ Bhg,
                 OutT* __restrict__ Cm, int M, int N, int K) {
    extern __shared__ half sm[];
    const uint32_t sbase = smem_u32(sm);
    const int tid = threadIdx.x;
    const int lane = tid & 31, wid = tid >> 5;
    const int warp_m = wid >> 2;  // 0..1  -> 64 rows each
    const int warp_n = wid & 3;   // 0..3  -> 32 cols each
    const int rowBase = blockIdx.y * BM;
    const int colBase = blockIdx.x * BN;

    // Staging maps: per thread 16 halves (2 x cp.async 16B) per tile
    const int ar = tid >> 1, ac = (tid & 1) * 16;   // A: 128 rows x 32 cols
    const int br = tid >> 3, bc = (tid & 7) * 16;   // B: 32 rows x 128 cols

    const half* Ag  = Ag_ + (size_t)(rowBase + ar) * K + ac;
    const half* Bg0 = Bhg + (size_t)br * N + colBase + bc;

    const uint32_t sAoff = (uint32_t)(ar * ALD + ac) * 2;
    const uint32_t sBoff = (uint32_t)A_B + (uint32_t)(br * BLD + bc) * 2;

    float acc[4][4][4] = {};

    const int nst = K / BKK;

    // prologue: stages 0 and 1
    #pragma unroll
    for (int p = 0; p < 2; p++) {
        uint32_t base = sbase + p * STAGE_B;
        const int k0 = p * BKK;
        const half* a  = Ag + k0;
        const half* b0 = Bg0 + (size_t)k0 * N;
        CP16(base + sAoff,      a);
        CP16(base + sAoff + 16, a + 8);
        CP16(base + sBoff,      b0);
        CP16(base + sBoff + 16, b0 + 8);
        CP_COMMIT();
    }

    int cur = 0;        // s % 3
    int nxt2 = 2;       // (s+2) % 3
    for (int s = 0; s < nst; s++) {
        CP_WAIT(1);         // stage s landed (FIFO completion)
        __syncthreads();    // stage s visible; stage s-1 compute done

        if (s + 2 < nst) {
            const int k0 = (s + 2) * BKK;
            uint32_t base = sbase + nxt2 * STAGE_B;
            const half* a  = Ag + k0;
            const half* b0 = Bg0 + (size_t)k0 * N;
            CP16(base + sAoff,      a);
            CP16(base + sAoff + 16, a + 8);
            CP16(base + sBoff,      b0);
            CP16(base + sBoff + 16, b0 + 8);
        }
        CP_COMMIT();        // always commit: uniform group counting

        // compute on stage cur
        {
            const uint32_t base = sbase + cur * STAGE_B;
            #pragma unroll
            for (int k16 = 0; k16 < 2; k16++) {
                uint32_t ah[4][4], bh[2][4];
                const int arow = warp_m * 64 + (lane & 15);
                const int acol = k16 * 16 + (lane >> 4) * 8;
                #pragma unroll
                for (int mi = 0; mi < 4; mi++)
                    LDSM_X4(ah[mi], base + (uint32_t)((arow + mi * 16) * ALD + acol) * 2);
                const int brow = k16 * 16 + (lane & 15);
                const int bcol = warp_n * 32 + (lane >> 4) * 8;
                #pragma unroll
                for (int ni = 0; ni < 2; ni++) {
                    uint32_t boff = (uint32_t)A_B + (uint32_t)(brow * BLD + bcol + ni * 16) * 2;
                    LDSM_X4T(bh[ni], base + boff);
                }
                #pragma unroll
                for (int mi = 0; mi < 4; mi++)
                    #pragma unroll
                    for (int nj = 0; nj < 4; nj++) {
                        const int ni = nj >> 1, ro = (nj & 1) * 2;
                        MMA16816(acc[mi][nj], ah[mi], bh[ni][ro], bh[ni][ro + 1]);
                    }
            }
        }

        cur = (cur == 2) ? 0 : cur + 1;
        nxt2 = (nxt2 == 2) ? 0 : nxt2 + 1;
    }

    // Epilogue
    const int g = lane >> 2;
    const int cc = (lane & 3) * 2;
    #pragma unroll
    for (int mi = 0; mi < 4; mi++) {
        const int r0 = rowBase + warp_m * 64 + mi * 16 + g;
        #pragma unroll
        for (int nj = 0; nj < 4; nj++) {
            const int c0 = colBase + warp_n * 32 + nj * 8 + cc;
            if constexpr (sizeof(OutT) == 4) {
                *(float2*)&Cm[(size_t)r0 * N + c0] =
                    make_float2(acc[mi][nj][0], acc[mi][nj][1]);
                *(float2*)&Cm[(size_t)(r0 + 8) * N + c0] =
                    make_float2(acc[mi][nj][2], acc[mi][nj][3]);
            } else {
                *(half2*)&Cm[(size_t)r0 * N + c0] =
                    __floats2half2_rn(acc[mi][nj][0], acc[mi][nj][1]);
                *(half2*)&Cm[(size_t)(r0 + 8) * N + c0] =
                    __floats2half2_rn(acc[mi][nj][2], acc[mi][nj][3]);
            }
        }
    }
}

// ---------------------------------------------------------------------------
// Fused fp32 -> fp16 conversion of u, B, C in ONE launch (8 elems/thread).
// ---------------------------------------------------------------------------
#define NU ((size_t)BATCH * LEN * IND)   // 16777216
#define NB ((size_t)IND * ST)            // 131072
#define NC ((size_t)ST * OUTD)           // 131072

__global__ __launch_bounds__(256)
void cvt_all_kernel(const float* __restrict__ u, const float* __restrict__ B,
                    const float* __restrict__ C) {
    size_t i = ((size_t)blockIdx.x * 256 + threadIdx.x) * 8;
    const float* in;
    half* out;
    if (i < NU)           { in = u + i;            out = g_uh + i; }
    else if (i < NU + NB) { in = B + (i - NU);     out = g_Bh + (i - NU); }
    else                  { in = C + (i - NU - NB); out = g_Ch + (i - NU - NB); }
    float4 v0 = *(const float4*)in;
    float4 v1 = *(const float4*)(in + 4);
    half2 h[4];
    h[0] = __floats2half2_rn(v0.x, v0.y);
    h[1] = __floats2half2_rn(v0.z, v0.w);
    h[2] = __floats2half2_rn(v1.x, v1.y);
    h[3] = __floats2half2_rn(v1.z, v1.w);
    *(uint4*)out = *(uint4*)h;
}

// ---------------------------------------------------------------------------
// Scan pass 1: per-chunk carry with zero initial state. Reads uB as fp16.
// ---------------------------------------------------------------------------
__global__ __launch_bounds__(ST / 2)
void scan1_kernel(const float* __restrict__ A) {
    const int n2 = threadIdx.x;
    const int c = blockIdx.x % NCH;
    const int b = blockIdx.x / NCH;
    const float2 a = ((const float2*)A)[n2];
    const half2* p = (const half2*)(g_uBh + ((size_t)(b * LEN + c * CHUNK)) * ST) + n2;
    float2 s = make_float2(0.0f, 0.0f);
    #pragma unroll
    for (int t = 0; t < CHUNK; t++) {
        float2 v = __half22float2(p[(size_t)t * (ST / 2)]);
        s.x = fmaf(a.x, s.x, v.x);
        s.y = fmaf(a.y, s.y, v.y);
    }
    ((float2*)g_carry)[(b * NCH + c) * (ST / 2) + n2] = s;
}

// ---------------------------------------------------------------------------
// Scan pass 2: inter-chunk exclusive prefix combine.
// ---------------------------------------------------------------------------
__global__ __launch_bounds__(ST / 2)
void scan2_kernel(const float* __restrict__ A, const float* __restrict__ x0) {
    const int n2 = threadIdx.x;
    const int b = blockIdx.x;
    const float2 a = ((const float2*)A)[n2];
    float2 aL = a;
    #pragma unroll
    for (int i = 0; i < 5; i++) { aL.x *= aL.x; aL.y *= aL.y; }   // a^32
    float2 s = ((const float2*)x0)[b * (ST / 2) + n2];
    #pragma unroll
    for (int c = 0; c < NCH; c++) {
        ((float2*)g_init)[(b * NCH + c) * (ST / 2) + n2] = s;
        float2 cv = ((const float2*)g_carry)[(b * NCH + c) * (ST / 2) + n2];
        s.x = fmaf(aL.x, s.x, cv.x);
        s.y = fmaf(aL.y, s.y, cv.y);
    }
}

// ---------------------------------------------------------------------------
// Scan pass 3: rescan per chunk from true init, write x as fp16 (GEMM2 input).
// ---------------------------------------------------------------------------
__global__ __launch_bounds__(ST / 2)
void scan3_kernel(const float* __restrict__ A, float* __restrict__ xlast) {
    const int n2 = threadIdx.x;
    const int c = blockIdx.x % NCH;
    const int b = blockIdx.x / NCH;
    const float2 a = ((const float2*)A)[n2];
    float2 s = ((const float2*)g_init)[(b * NCH + c) * (ST / 2) + n2];
    const size_t base = ((size_t)(b * LEN + c * CHUNK)) * (ST / 2) + n2;
    const half2* pin = (const half2*)g_uBh;
    half2* pout = (half2*)g_xh;
    #pragma unroll
    for (int t = 0; t < CHUNK; t++) {
        float2 v = __half22float2(pin[base + (size_t)t * (ST / 2)]);
        s.x = fmaf(a.x, s.x, v.x);
        s.y = fmaf(a.y, s.y, v.y);
        pout[base + (size_t)t * (ST / 2)] = __floats2half2_rn(s.x, s.y);
    }
    if (c == NCH - 1) {
        ((float2*)xlast)[b * (ST / 2) + n2] = s;
    }
}

// ---------------------------------------------------------------------------
// kernel_launch
// Inputs: u [8,4096,512], x0 [8,256], A [256], B [512,256], C [256,512]
// Output: y [8,4096,512] flattened, then x_last [8,256].
// ---------------------------------------------------------------------------
extern "C" void kernel_launch(void* const* d_in, const int* in_sizes, int n_in,
                              void* d_out, int out_size) {
    const float* u  = (const float*)d_in[0];
    const float* x0 = (const float*)d_in[1];
    const float* A  = (const float*)d_in[2];
    const float* B  = (const float*)d_in[3];
    const float* C  = (const float*)d_in[4];

    float* y = (float*)d_out;
    float* xlast = y + (size_t)BATCH * LEN * OUTD;

    half *uBh_ptr, *uh_ptr, *xh_ptr, *Bh_ptr, *Ch_ptr;
    cudaGetSymbolAddress((void**)&uBh_ptr, g_uBh);
    cudaGetSymbolAddress((void**)&uh_ptr,  g_uh);
    cudaGetSymbolAddress((void**)&xh_ptr,  g_xh);
    cudaGetSymbolAddress((void**)&Bh_ptr,  g_Bh);
    cudaGetSymbolAddress((void**)&Ch_ptr,  g_Ch);

    cudaFuncSetAttribute(gemm_hmma_h<half>,
                         cudaFuncAttributeMaxDynamicSharedMemorySize, GEMM_SMEM);
    cudaFuncSetAttribute(gemm_hmma_h<float>,
                         cudaFuncAttributeMaxDynamicSharedMemorySize, GEMM_SMEM);

    const int M = BATCH * LEN;   // 32768

    // Fused pre-pass: u, B, C -> fp16 in one launch
    {
        size_t total = NU + NB + NC;
        cvt_all_kernel<<<(unsigned)(total / (256 * 8)), 256>>>(u, B, C);
    }

    // GEMM1: uBh = uh @ Bh   [32768,512] @ [512,256] -> fp16
    {
        dim3 grid(ST / BN, M / BM);
        gemm_hmma_h<half><<<grid, 256, GEMM_SMEM>>>(uh_ptr, Bh_ptr, uBh_ptr, M, ST, IND);
    }

    // Scan
    scan1_kernel<<<BATCH * NCH, ST / 2>>>(A);
    scan2_kernel<<<BATCH, ST / 2>>>(A, x0);
    scan3_kernel<<<BATCH * NCH, ST / 2>>>(A, xlast);

    // GEMM2: y = xh @ Ch    [32768,256] @ [256,512] -> fp32
    {
        dim3 grid(OUTD / BN, M / BM);
        gemm_hmma_h<float><<<grid, 256, GEMM_SMEM>>>(xh_ptr, Ch_ptr, y, M, OUTD, ST);
    }
}

// round 15
// speedup vs baseline: 2.0334x; 1.2184x over previous
#include <cuda_runtime.h>
#include <cuda_fp16.h>
#include <cstdint>
#include <cstddef>

// Problem constants
#define BATCH 8
#define LEN   4096
#define IND   512
#define ST    256
#define OUTD  512

#define CHUNK 32
#define NCH   (LEN / CHUNK)   // 128

// Scratch in device globals (no allocation allowed)
__device__ half  g_uBh[(size_t)BATCH * LEN * ST];     // 16 MB (uB as fp16)
__device__ half  g_uh[(size_t)BATCH * LEN * IND];     // 32 MB (u as fp16)
__device__ half  g_xh[(size_t)BATCH * LEN * ST];      // 16 MB (x as fp16)
__device__ float g_carry[BATCH * NCH * ST];
__device__ float g_init [BATCH * NCH * ST];
__device__ half  g_Bh[IND * ST];                      // B as fp16
__device__ half  g_Ch[ST * OUTD];                     // C as fp16

// ---------------------------------------------------------------------------
// HMMA single-pass fp16 GEMM:  Cm[M,N](OutT) = Ah[M,K](fp16) @ Bh[K,N](fp16)
// CTA tile 128x128x32, 8 warps as 2m x 4n, warp tile 64x32, fp32 accumulate.
// 3-stage cp.async pipeline, one __syncthreads per K-stage.
// ---------------------------------------------------------------------------
#define BM 128
#define BN 128
#define BKK 32
#define ALD 40    // A smem leading dim in halves (pad 32->40)
#define BLD 136   // B smem leading dim in halves (pad 128->136)
#define A_SZ (BM * ALD)                 // 5120 halves
#define B_SZ (BKK * BLD)                // 4352 halves
#define A_B  (A_SZ * 2)                 // 10240 bytes
#define B_B  (B_SZ * 2)                 // 8704 bytes
#define STAGE_B (A_B + B_B)             // 18944 bytes
#define NSTAGE 3
#define GEMM_SMEM (NSTAGE * STAGE_B)    // 56832 bytes

__device__ __forceinline__ uint32_t smem_u32(const void* p) {
    uint32_t a;
    asm("{ .reg .u64 t; cvta.to.shared.u64 t, %1; cvt.u32.u64 %0, t; }"
        : "=r"(a) : "l"(p));
    return a;
}

#define CP16(saddr, gptr) \
    asm volatile("cp.async.cg.shared.global [%0], [%1], 16;" \
        :: "r"(saddr), "l"(gptr))
#define CP_COMMIT() asm volatile("cp.async.commit_group;" ::: "memory")
#define CP_WAIT(n)  asm volatile("cp.async.wait_group %0;" :: "n"(n) : "memory")

#define LDSM_X4(r, addr) \
    asm volatile("ldmatrix.sync.aligned.m8n8.x4.shared.b16 {%0,%1,%2,%3}, [%4];" \
        : "=r"((r)[0]), "=r"((r)[1]), "=r"((r)[2]), "=r"((r)[3]) : "r"(addr))

#define LDSM_X4T(r, addr) \
    asm volatile("ldmatrix.sync.aligned.m8n8.x4.trans.shared.b16 {%0,%1,%2,%3}, [%4];" \
        : "=r"((r)[0]), "=r"((r)[1]), "=r"((r)[2]), "=r"((r)[3]) : "r"(addr))

#define MMA16816(d, a, b0, b1) \
    asm volatile("mma.sync.aligned.m16n8k16.row.col.f32.f16.f16.f32 " \
        "{%0,%1,%2,%3}, {%4,%5,%6,%7}, {%8,%9}, {%0,%1,%2,%3};" \
        : "+f"((d)[0]), "+f"((d)[1]), "+f"((d)[2]), "+f"((d)[3]) \
        : "r"((a)[0]), "r"((a)[1]), "r"((a)[2]), "r"((a)[3]), \
          "r"(b0), "r"(b1))

template <typename OutT>
__global__ __launch_bounds__(256, 2)
void gemm_hmma_h(const half* __restrict__ Ag_, const half* __restrict__ Bhg,
                 OutT* __restrict__ Cm, int M, int N, int K) {
    extern __shared__ half sm[];
    const uint32_t sbase = smem_u32(sm);
    const int tid = threadIdx.x;
    const int lane = tid & 31, wid = tid >> 5;
    const int warp_m = wid >> 2;  // 0..1  -> 64 rows each
    const int warp_n = wid & 3;   // 0..3  -> 32 cols each
    const int rowBase = blockIdx.y * BM;
    const int colBase = blockIdx.x * BN;

    // Staging maps: per thread 16 halves (2 x cp.async 16B) per tile
    const int ar = tid >> 1, ac = (tid & 1) * 16;   // A: 128 rows x 32 cols
    const int br = tid >> 3, bc = (tid & 7) * 16;   // B: 32 rows x 128 cols

    const half* Ag  = Ag_ + (size_t)(rowBase + ar) * K + ac;
    const half* Bg0 = Bhg + (size_t)br * N + colBase + bc;

    const uint32_t sAoff = (uint32_t)(ar * ALD + ac) * 2;
    const uint32_t sBoff = (uint32_t)A_B + (uint32_t)(br * BLD + bc) * 2;

    float acc[4][4][4] = {};

    const int nst = K / BKK;

    // prologue: stages 0 and 1
    #pragma unroll
    for (int p = 0; p < 2; p++) {
        uint32_t base = sbase + p * STAGE_B;
        const int k0 = p * BKK;
        const half* a  = Ag + k0;
        const half* b0 = Bg0 + (size_t)k0 * N;
        CP16(base + sAoff,      a);
        CP16(base + sAoff + 16, a + 8);
        CP16(base + sBoff,      b0);
        CP16(base + sBoff + 16, b0 + 8);
        CP_COMMIT();
    }

    int cur = 0;        // s % 3
    int nxt2 = 2;       // (s+2) % 3
    for (int s = 0; s < nst; s++) {
        CP_WAIT(1);         // stage s landed (FIFO completion)
        __syncthreads();    // stage s visible; stage s-1 compute done

        if (s + 2 < nst) {
            const int k0 = (s + 2) * BKK;
            uint32_t base = sbase + nxt2 * STAGE_B;
            const half* a  = Ag + k0;
            const half* b0 = Bg0 + (size_t)k0 * N;
            CP16(base + sAoff,      a);
            CP16(base + sAoff + 16, a + 8);
            CP16(base + sBoff,      b0);
            CP16(base + sBoff + 16, b0 + 8);
        }
        CP_COMMIT();        // always commit: uniform group counting

        // compute on stage cur
        {
            const uint32_t base = sbase + cur * STAGE_B;
            #pragma unroll
            for (int k16 = 0; k16 < 2; k16++) {
                uint32_t ah[4][4], bh[2][4];
                const int arow = warp_m * 64 + (lane & 15);
                const int acol = k16 * 16 + (lane >> 4) * 8;
                #pragma unroll
                for (int mi = 0; mi < 4; mi++)
                    LDSM_X4(ah[mi], base + (uint32_t)((arow + mi * 16) * ALD + acol) * 2);
                const int brow = k16 * 16 + (lane & 15);
                const int bcol = warp_n * 32 + (lane >> 4) * 8;
                #pragma unroll
                for (int ni = 0; ni < 2; ni++) {
                    uint32_t boff = (uint32_t)A_B + (uint32_t)(brow * BLD + bcol + ni * 16) * 2;
                    LDSM_X4T(bh[ni], base + boff);
                }
                #pragma unroll
                for (int mi = 0; mi < 4; mi++)
                    #pragma unroll
                    for (int nj = 0; nj < 4; nj++) {
                        const int ni = nj >> 1, ro = (nj & 1) * 2;
                        MMA16816(acc[mi][nj], ah[mi], bh[ni][ro], bh[ni][ro + 1]);
                    }
            }
        }

        cur = (cur == 2) ? 0 : cur + 1;
        nxt2 = (nxt2 == 2) ? 0 : nxt2 + 1;
    }

    // Epilogue
    const int g = lane >> 2;
    const int cc = (lane & 3) * 2;
    #pragma unroll
    for (int mi = 0; mi < 4; mi++) {
        const int r0 = rowBase + warp_m * 64 + mi * 16 + g;
        #pragma unroll
        for (int nj = 0; nj < 4; nj++) {
            const int c0 = colBase + warp_n * 32 + nj * 8 + cc;
            if constexpr (sizeof(OutT) == 4) {
                *(float2*)&Cm[(size_t)r0 * N + c0] =
                    make_float2(acc[mi][nj][0], acc[mi][nj][1]);
                *(float2*)&Cm[(size_t)(r0 + 8) * N + c0] =
                    make_float2(acc[mi][nj][2], acc[mi][nj][3]);
            } else {
                *(half2*)&Cm[(size_t)r0 * N + c0] =
                    __floats2half2_rn(acc[mi][nj][0], acc[mi][nj][1]);
                *(half2*)&Cm[(size_t)(r0 + 8) * N + c0] =
                    __floats2half2_rn(acc[mi][nj][2], acc[mi][nj][3]);
            }
        }
    }
}

// ---------------------------------------------------------------------------
// Fused fp32 -> fp16 conversion of u, B, C in ONE launch (8 elems/thread).
// ---------------------------------------------------------------------------
#define NU ((size_t)BATCH * LEN * IND)   // 16777216
#define NB ((size_t)IND * ST)            // 131072
#define NC ((size_t)ST * OUTD)           // 131072

__global__ __launch_bounds__(256)
void cvt_all_kernel(const float* __restrict__ u, const float* __restrict__ B,
                    const float* __restrict__ C) {
    size_t i = ((size_t)blockIdx.x * 256 + threadIdx.x) * 8;
    const float* in;
    half* out;
    if (i < NU)           { in = u + i;            out = g_uh + i; }
    else if (i < NU + NB) { in = B + (i - NU);     out = g_Bh + (i - NU); }
    else                  { in = C + (i - NU - NB); out = g_Ch + (i - NU - NB); }
    float4 v0 = *(const float4*)in;
    float4 v1 = *(const float4*)(in + 4);
    half2 h[4];
    h[0] = __floats2half2_rn(v0.x, v0.y);
    h[1] = __floats2half2_rn(v0.z, v0.w);
    h[2] = __floats2half2_rn(v1.x, v1.y);
    h[3] = __floats2half2_rn(v1.z, v1.w);
    *(uint4*)out = *(uint4*)h;
}

// ---------------------------------------------------------------------------
// Scan pass 1: per-chunk carry with zero initial state. Reads uB as fp16.
// ---------------------------------------------------------------------------
__global__ __launch_bounds__(ST / 2)
void scan1_kernel(const float* __restrict__ A) {
    const int n2 = threadIdx.x;
    const int c = blockIdx.x % NCH;
    const int b = blockIdx.x / NCH;
    const float2 a = ((const float2*)A)[n2];
    const half2* p = (const half2*)(g_uBh + ((size_t)(b * LEN + c * CHUNK)) * ST) + n2;
    float2 s = make_float2(0.0f, 0.0f);
    #pragma unroll
    for (int t = 0; t < CHUNK; t++) {
        float2 v = __half22float2(p[(size_t)t * (ST / 2)]);
        s.x = fmaf(a.x, s.x, v.x);
        s.y = fmaf(a.y, s.y, v.y);
    }
    ((float2*)g_carry)[(b * NCH + c) * (ST / 2) + n2] = s;
}

// ---------------------------------------------------------------------------
// Scan pass 2: inter-chunk exclusive prefix combine.
// Carries prefetched in register batches of 16 (MLP=16) so the only serial
// dependency is the 4-cycle FMA chain, not the memory latency.
// ---------------------------------------------------------------------------
#define S2B 16
__global__ __launch_bounds__(ST / 2)
void scan2_kernel(const float* __restrict__ A, const float* __restrict__ x0) {
    const int n2 = threadIdx.x;
    const int b = blockIdx.x;
    const float2 a = ((const float2*)A)[n2];
    float2 aL = a;
    #pragma unroll
    for (int i = 0; i < 5; i++) { aL.x *= aL.x; aL.y *= aL.y; }   // a^32
    float2 s = ((const float2*)x0)[b * (ST / 2) + n2];
    const float2* carry = (const float2*)g_carry + (size_t)b * NCH * (ST / 2) + n2;
    float2* init = (float2*)g_init + (size_t)b * NCH * (ST / 2) + n2;

    #pragma unroll
    for (int g = 0; g < NCH / S2B; g++) {
        float2 buf[S2B];
        #pragma unroll
        for (int i = 0; i < S2B; i++)
            buf[i] = carry[(size_t)(g * S2B + i) * (ST / 2)];
        #pragma unroll
        for (int i = 0; i < S2B; i++) {
            init[(size_t)(g * S2B + i) * (ST / 2)] = s;
            s.x = fmaf(aL.x, s.x, buf[i].x);
            s.y = fmaf(aL.y, s.y, buf[i].y);
        }
    }
}

// ---------------------------------------------------------------------------
// Scan pass 3: rescan per chunk from true init, write x as fp16 (GEMM2 input).
// ---------------------------------------------------------------------------
__global__ __launch_bounds__(ST / 2)
void scan3_kernel(const float* __restrict__ A, float* __restrict__ xlast) {
    const int n2 = threadIdx.x;
    const int c = blockIdx.x % NCH;
    const int b = blockIdx.x / NCH;
    const float2 a = ((const float2*)A)[n2];
    float2 s = ((const float2*)g_init)[(b * NCH + c) * (ST / 2) + n2];
    const size_t base = ((size_t)(b * LEN + c * CHUNK)) * (ST / 2) + n2;
    const half2* pin = (const half2*)g_uBh;
    half2* pout = (half2*)g_xh;
    #pragma unroll
    for (int t = 0; t < CHUNK; t++) {
        float2 v = __half22float2(pin[base + (size_t)t * (ST / 2)]);
        s.x = fmaf(a.x, s.x, v.x);
        s.y = fmaf(a.y, s.y, v.y);
        pout[base + (size_t)t * (ST / 2)] = __floats2half2_rn(s.x, s.y);
    }
    if (c == NCH - 1) {
        ((float2*)xlast)[b * (ST / 2) + n2] = s;
    }
}

// ---------------------------------------------------------------------------
// kernel_launch
// Inputs: u [8,4096,512], x0 [8,256], A [256], B [512,256], C [256,512]
// Output: y [8,4096,512] flattened, then x_last [8,256].
// ---------------------------------------------------------------------------
extern "C" void kernel_launch(void* const* d_in, const int* in_sizes, int n_in,
                              void* d_out, int out_size) {
    const float* u  = (const float*)d_in[0];
    const float* x0 = (const float*)d_in[1];
    const float* A  = (const float*)d_in[2];
    const float* B  = (const float*)d_in[3];
    const float* C  = (const float*)d_in[4];

    float* y = (float*)d_out;
    float* xlast = y + (size_t)BATCH * LEN * OUTD;

    half *uBh_ptr, *uh_ptr, *xh_ptr, *Bh_ptr, *Ch_ptr;
    cudaGetSymbolAddress((void**)&uBh_ptr, g_uBh);
    cudaGetSymbolAddress((void**)&uh_ptr,  g_uh);
    cudaGetSymbolAddress((void**)&xh_ptr,  g_xh);
    cudaGetSymbolAddress((void**)&Bh_ptr,  g_Bh);
    cudaGetSymbolAddress((void**)&Ch_ptr,  g_Ch);

    cudaFuncSetAttribute(gemm_hmma_h<half>,
                         cudaFuncAttributeMaxDynamicSharedMemorySize, GEMM_SMEM);
    cudaFuncSetAttribute(gemm_hmma_h<float>,
                         cudaFuncAttributeMaxDynamicSharedMemorySize, GEMM_SMEM);

    const int M = BATCH * LEN;   // 32768

    // Fused pre-pass: u, B, C -> fp16 in one launch
    {
        size_t total = NU + NB + NC;
        cvt_all_kernel<<<(unsigned)(total / (256 * 8)), 256>>>(u, B, C);
    }

    // GEMM1: uBh = uh @ Bh   [32768,512] @ [512,256] -> fp16
    {
        dim3 grid(ST / BN, M / BM);
        gemm_hmma_h<half><<<grid, 256, GEMM_SMEM>>>(uh_ptr, Bh_ptr, uBh_ptr, M, ST, IND);
    }

    // Scan
    scan1_kernel<<<BATCH * NCH, ST / 2>>>(A);
    scan2_kernel<<<BATCH, ST / 2>>>(A, x0);
    scan3_kernel<<<BATCH * NCH, ST / 2>>>(A, xlast);

    // GEMM2: y = xh @ Ch    [32768,256] @ [256,512] -> fp32
    {
        dim3 grid(OUTD / BN, M / BM);
        gemm_hmma_h<float><<<grid, 256, GEMM_SMEM>>>(xh_ptr, Ch_ptr, y, M, OUTD, ST);
    }
}

// round 16
// speedup vs baseline: 2.1177x; 1.0415x over previous
#include <cuda_runtime.h>
#include <cuda_fp16.h>
#include <cstdint>
#include <cstddef>

// Problem constants
#define BATCH 8
#define LEN   4096
#define IND   512
#define ST    256
#define OUTD  512

#define CHUNK 32
#define NCH   (LEN / CHUNK)   // 128

// Scratch in device globals (no allocation allowed)
__device__ half  g_uBh[(size_t)BATCH * LEN * ST];     // 16 MB (uB as fp16)
__device__ half  g_uh[(size_t)BATCH * LEN * IND];     // 32 MB (u as fp16)
__device__ half  g_xh[(size_t)BATCH * LEN * ST];      // 16 MB (x as fp16)
__device__ float g_carry[BATCH * NCH * ST];
__device__ float g_init [BATCH * NCH * ST];
__device__ half  g_Bh[IND * ST];                      // B as fp16
__device__ half  g_Ch[ST * OUTD];                     // C as fp16

// ---------------------------------------------------------------------------
// HMMA single-pass fp16 GEMM:  Cm[M,N](OutT) = Ah[M,K](fp16) @ Bh[K,N](fp16)
// CTA tile 128x128x32, 8 warps as 2m x 4n, warp tile 64x32, fp32 accumulate.
// 3-stage cp.async pipeline, one __syncthreads per K-stage.
// ---------------------------------------------------------------------------
#define BM 128
#define BN 128
#define BKK 32
#define ALD 40    // A smem leading dim in halves (pad 32->40)
#define BLD 136   // B smem leading dim in halves (pad 128->136)
#define A_SZ (BM * ALD)                 // 5120 halves
#define B_SZ (BKK * BLD)                // 4352 halves
#define A_B  (A_SZ * 2)                 // 10240 bytes
#define B_B  (B_SZ * 2)                 // 8704 bytes
#define STAGE_B (A_B + B_B)             // 18944 bytes
#define NSTAGE 3
#define GEMM_SMEM (NSTAGE * STAGE_B)    // 56832 bytes

__device__ __forceinline__ uint32_t smem_u32(const void* p) {
    uint32_t a;
    asm("{ .reg .u64 t; cvta.to.shared.u64 t, %1; cvt.u32.u64 %0, t; }"
        : "=r"(a) : "l"(p));
    return a;
}

#define CP16(saddr, gptr) \
    asm volatile("cp.async.cg.shared.global [%0], [%1], 16;" \
        :: "r"(saddr), "l"(gptr))
#define CP_COMMIT() asm volatile("cp.async.commit_group;" ::: "memory")
#define CP_WAIT(n)  asm volatile("cp.async.wait_group %0;" :: "n"(n) : "memory")

#define LDSM_X4(r, addr) \
    asm volatile("ldmatrix.sync.aligned.m8n8.x4.shared.b16 {%0,%1,%2,%3}, [%4];" \
        : "=r"((r)[0]), "=r"((r)[1]), "=r"((r)[2]), "=r"((r)[3]) : "r"(addr))

#define LDSM_X4T(r, addr) \
    asm volatile("ldmatrix.sync.aligned.m8n8.x4.trans.shared.b16 {%0,%1,%2,%3}, [%4];" \
        : "=r"((r)[0]), "=r"((r)[1]), "=r"((r)[2]), "=r"((r)[3]) : "r"(addr))

#define MMA16816(d, a, b0, b1) \
    asm volatile("mma.sync.aligned.m16n8k16.row.col.f32.f16.f16.f32 " \
        "{%0,%1,%2,%3}, {%4,%5,%6,%7}, {%8,%9}, {%0,%1,%2,%3};" \
        : "+f"((d)[0]), "+f"((d)[1]), "+f"((d)[2]), "+f"((d)[3]) \
        : "r"((a)[0]), "r"((a)[1]), "r"((a)[2]), "r"((a)[3]), \
          "r"(b0), "r"(b1))

template <typename OutT>
__global__ __launch_bounds__(256, 2)
void gemm_hmma_h(const half* __restrict__ Ag_, const half* __restrict__ Bhg,
                 OutT* __restrict__ Cm, int M, int N, int K) {
    extern __shared__ half sm[];
    const uint32_t sbase = smem_u32(sm);
    const int tid = threadIdx.x;
    const int lane = tid & 31, wid = tid >> 5;
    const int warp_m = wid >> 2;  // 0..1  -> 64 rows each
    const int warp_n = wid & 3;   // 0..3  -> 32 cols each
    const int rowBase = blockIdx.y * BM;
    const int colBase = blockIdx.x * BN;

    // Staging maps: per thread 16 halves (2 x cp.async 16B) per tile
    const int ar = tid >> 1, ac = (tid & 1) * 16;   // A: 128 rows x 32 cols
    const int br = tid >> 3, bc = (tid & 7) * 16;   // B: 32 rows x 128 cols

    const half* Ag  = Ag_ + (size_t)(rowBase + ar) * K + ac;
    const half* Bg0 = Bhg + (size_t)br * N + colBase + bc;

    const uint32_t sAoff = (uint32_t)(ar * ALD + ac) * 2;
    const uint32_t sBoff = (uint32_t)A_B + (uint32_t)(br * BLD + bc) * 2;

    float acc[4][4][4] = {};

    const int nst = K / BKK;

    // prologue: stages 0 and 1
    #pragma unroll
    for (int p = 0; p < 2; p++) {
        uint32_t base = sbase + p * STAGE_B;
        const int k0 = p * BKK;
        const half* a  = Ag + k0;
        const half* b0 = Bg0 + (size_t)k0 * N;
        CP16(base + sAoff,      a);
        CP16(base + sAoff + 16, a + 8);
        CP16(base + sBoff,      b0);
        CP16(base + sBoff + 16, b0 + 8);
        CP_COMMIT();
    }

    int cur = 0;        // s % 3
    int nxt2 = 2;       // (s+2) % 3
    for (int s = 0; s < nst; s++) {
        CP_WAIT(1);         // stage s landed (FIFO completion)
        __syncthreads();    // stage s visible; stage s-1 compute done

        if (s + 2 < nst) {
            const int k0 = (s + 2) * BKK;
            uint32_t base = sbase + nxt2 * STAGE_B;
            const half* a  = Ag + k0;
            const half* b0 = Bg0 + (size_t)k0 * N;
            CP16(base + sAoff,      a);
            CP16(base + sAoff + 16, a + 8);
            CP16(base + sBoff,      b0);
            CP16(base + sBoff + 16, b0 + 8);
        }
        CP_COMMIT();        // always commit: uniform group counting

        // compute on stage cur
        {
            const uint32_t base = sbase + cur * STAGE_B;
            #pragma unroll
            for (int k16 = 0; k16 < 2; k16++) {
                uint32_t ah[4][4], bh[2][4];
                const int arow = warp_m * 64 + (lane & 15);
                const int acol = k16 * 16 + (lane >> 4) * 8;
                #pragma unroll
                for (int mi = 0; mi < 4; mi++)
                    LDSM_X4(ah[mi], base + (uint32_t)((arow + mi * 16) * ALD + acol) * 2);
                const int brow = k16 * 16 + (lane & 15);
                const int bcol = warp_n * 32 + (lane >> 4) * 8;
                #pragma unroll
                for (int ni = 0; ni < 2; ni++) {
                    uint32_t boff = (uint32_t)A_B + (uint32_t)(brow * BLD + bcol + ni * 16) * 2;
                    LDSM_X4T(bh[ni], base + boff);
                }
                #pragma unroll
                for (int mi = 0; mi < 4; mi++)
                    #pragma unroll
                    for (int nj = 0; nj < 4; nj++) {
                        const int ni = nj >> 1, ro = (nj & 1) * 2;
                        MMA16816(acc[mi][nj], ah[mi], bh[ni][ro], bh[ni][ro + 1]);
                    }
            }
        }

        cur = (cur == 2) ? 0 : cur + 1;
        nxt2 = (nxt2 == 2) ? 0 : nxt2 + 1;
    }

    // Epilogue
    const int g = lane >> 2;
    const int cc = (lane & 3) * 2;
    #pragma unroll
    for (int mi = 0; mi < 4; mi++) {
        const int r0 = rowBase + warp_m * 64 + mi * 16 + g;
        #pragma unroll
        for (int nj = 0; nj < 4; nj++) {
            const int c0 = colBase + warp_n * 32 + nj * 8 + cc;
            if constexpr (sizeof(OutT) == 4) {
                *(float2*)&Cm[(size_t)r0 * N + c0] =
                    make_float2(acc[mi][nj][0], acc[mi][nj][1]);
                *(float2*)&Cm[(size_t)(r0 + 8) * N + c0] =
                    make_float2(acc[mi][nj][2], acc[mi][nj][3]);
            } else {
                *(half2*)&Cm[(size_t)r0 * N + c0] =
                    __floats2half2_rn(acc[mi][nj][0], acc[mi][nj][1]);
                *(half2*)&Cm[(size_t)(r0 + 8) * N + c0] =
                    __floats2half2_rn(acc[mi][nj][2], acc[mi][nj][3]);
            }
        }
    }
}

// ---------------------------------------------------------------------------
// Fused fp32 -> fp16 conversion of u, B, C in ONE launch (8 elems/thread).
// ---------------------------------------------------------------------------
#define NU ((size_t)BATCH * LEN * IND)   // 16777216
#define NB ((size_t)IND * ST)            // 131072
#define NC ((size_t)ST * OUTD)           // 131072

__global__ __launch_bounds__(256)
void cvt_all_kernel(const float* __restrict__ u, const float* __restrict__ B,
                    const float* __restrict__ C) {
    size_t i = ((size_t)blockIdx.x * 256 + threadIdx.x) * 8;
    const float* in;
    half* out;
    if (i < NU)           { in = u + i;            out = g_uh + i; }
    else if (i < NU + NB) { in = B + (i - NU);     out = g_Bh + (i - NU); }
    else                  { in = C + (i - NU - NB); out = g_Ch + (i - NU - NB); }
    float4 v0 = *(const float4*)in;
    float4 v1 = *(const float4*)(in + 4);
    half2 h[4];
    h[0] = __floats2half2_rn(v0.x, v0.y);
    h[1] = __floats2half2_rn(v0.z, v0.w);
    h[2] = __floats2half2_rn(v1.x, v1.y);
    h[3] = __floats2half2_rn(v1.z, v1.w);
    *(uint4*)out = *(uint4*)h;
}

// ---------------------------------------------------------------------------
// Scan pass 1: per-chunk carry with zero initial state. Reads uB as fp16.
// Loads register-batched (8) to expose MLP ahead of the serial fma chain.
// ---------------------------------------------------------------------------
#define S1B 8
__global__ __launch_bounds__(ST / 2)
void scan1_kernel(const float* __restrict__ A) {
    const int n2 = threadIdx.x;
    const int c = blockIdx.x % NCH;
    const int b = blockIdx.x / NCH;
    const float2 a = ((const float2*)A)[n2];
    const half2* p = (const half2*)(g_uBh + ((size_t)(b * LEN + c * CHUNK)) * ST) + n2;
    float2 s = make_float2(0.0f, 0.0f);
    #pragma unroll
    for (int g = 0; g < CHUNK / S1B; g++) {
        half2 buf[S1B];
        #pragma unroll
        for (int i = 0; i < S1B; i++)
            buf[i] = p[(size_t)(g * S1B + i) * (ST / 2)];
        #pragma unroll
        for (int i = 0; i < S1B; i++) {
            float2 v = __half22float2(buf[i]);
            s.x = fmaf(a.x, s.x, v.x);
            s.y = fmaf(a.y, s.y, v.y);
        }
    }
    ((float2*)g_carry)[(b * NCH + c) * (ST / 2) + n2] = s;
}

// ---------------------------------------------------------------------------
// Scan pass 2: inter-chunk exclusive prefix combine.
// Carries prefetched in register batches of 32 (MLP=32); only the 4-cycle
// fma chain is serial.
// ---------------------------------------------------------------------------
#define S2B 32
__global__ __launch_bounds__(ST / 2)
void scan2_kernel(const float* __restrict__ A, const float* __restrict__ x0) {
    const int n2 = threadIdx.x;
    const int b = blockIdx.x;
    const float2 a = ((const float2*)A)[n2];
    float2 aL = a;
    #pragma unroll
    for (int i = 0; i < 5; i++) { aL.x *= aL.x; aL.y *= aL.y; }   // a^32
    float2 s = ((const float2*)x0)[b * (ST / 2) + n2];
    const float2* carry = (const float2*)g_carry + (size_t)b * NCH * (ST / 2) + n2;
    float2* init = (float2*)g_init + (size_t)b * NCH * (ST / 2) + n2;

    #pragma unroll
    for (int g = 0; g < NCH / S2B; g++) {
        float2 buf[S2B];
        #pragma unroll
        for (int i = 0; i < S2B; i++)
            buf[i] = carry[(size_t)(g * S2B + i) * (ST / 2)];
        #pragma unroll
        for (int i = 0; i < S2B; i++) {
            init[(size_t)(g * S2B + i) * (ST / 2)] = s;
            s.x = fmaf(aL.x, s.x, buf[i].x);
            s.y = fmaf(aL.y, s.y, buf[i].y);
        }
    }
}

// ---------------------------------------------------------------------------
// Scan pass 3: rescan per chunk from true init, write x as fp16 (GEMM2 input).
// Loads register-batched (8) to expose MLP ahead of the serial fma chain.
// ---------------------------------------------------------------------------
__global__ __launch_bounds__(ST / 2)
void scan3_kernel(const float* __restrict__ A, float* __restrict__ xlast) {
    const int n2 = threadIdx.x;
    const int c = blockIdx.x % NCH;
    const int b = blockIdx.x / NCH;
    const float2 a = ((const float2*)A)[n2];
    float2 s = ((const float2*)g_init)[(b * NCH + c) * (ST / 2) + n2];
    const size_t base = ((size_t)(b * LEN + c * CHUNK)) * (ST / 2) + n2;
    const half2* pin = (const half2*)g_uBh;
    half2* pout = (half2*)g_xh;
    #pragma unroll
    for (int g = 0; g < CHUNK / S1B; g++) {
        half2 buf[S1B];
        #pragma unroll
        for (int i = 0; i < S1B; i++)
            buf[i] = pin[base + (size_t)(g * S1B + i) * (ST / 2)];
        #pragma unroll
        for (int i = 0; i < S1B; i++) {
            float2 v = __half22float2(buf[i]);
            s.x = fmaf(a.x, s.x, v.x);
            s.y = fmaf(a.y, s.y, v.y);
            pout[base + (size_t)(g * S1B + i) * (ST / 2)] = __floats2half2_rn(s.x, s.y);
        }
    }
    if (c == NCH - 1) {
        ((float2*)xlast)[b * (ST / 2) + n2] = s;
    }
}

// ---------------------------------------------------------------------------
// kernel_launch
// Inputs: u [8,4096,512], x0 [8,256], A [256], B [512,256], C [256,512]
// Output: y [8,4096,512] flattened, then x_last [8,256].
// ---------------------------------------------------------------------------
extern "C" void kernel_launch(void* const* d_in, const int* in_sizes, int n_in,
                              void* d_out, int out_size) {
    const float* u  = (const float*)d_in[0];
    const float* x0 = (const float*)d_in[1];
    const float* A  = (const float*)d_in[2];
    const float* B  = (const float*)d_in[3];
    const float* C  = (const float*)d_in[4];

    float* y = (float*)d_out;
    float* xlast = y + (size_t)BATCH * LEN * OUTD;

    half *uBh_ptr, *uh_ptr, *xh_ptr, *Bh_ptr, *Ch_ptr;
    cudaGetSymbolAddress((void**)&uBh_ptr, g_uBh);
    cudaGetSymbolAddress((void**)&uh_ptr,  g_uh);
    cudaGetSymbolAddress((void**)&xh_ptr,  g_xh);
    cudaGetSymbolAddress((void**)&Bh_ptr,  g_Bh);
    cudaGetSymbolAddress((void**)&Ch_ptr,  g_Ch);

    cudaFuncSetAttribute(gemm_hmma_h<half>,
                         cudaFuncAttributeMaxDynamicSharedMemorySize, GEMM_SMEM);
    cudaFuncSetAttribute(gemm_hmma_h<float>,
                         cudaFuncAttributeMaxDynamicSharedMemorySize, GEMM_SMEM);

    const int M = BATCH * LEN;   // 32768

    // Fused pre-pass: u, B, C -> fp16 in one launch
    {
        size_t total = NU + NB + NC;
        cvt_all_kernel<<<(unsigned)(total / (256 * 8)), 256>>>(u, B, C);
    }

    // GEMM1: uBh = uh @ Bh   [32768,512] @ [512,256] -> fp16
    {
        dim3 grid(ST / BN, M / BM);
        gemm_hmma_h<half><<<grid, 256, GEMM_SMEM>>>(uh_ptr, Bh_ptr, uBh_ptr, M, ST, IND);
    }

    // Scan
    scan1_kernel<<<BATCH * NCH, ST / 2>>>(A);
    scan2_kernel<<<BATCH, ST / 2>>>(A, x0);
    scan3_kernel<<<BATCH * NCH, ST / 2>>>(A, xlast);

    // GEMM2: y = xh @ Ch    [32768,256] @ [256,512] -> fp32
    {
        dim3 grid(OUTD / BN, M / BM);
        gemm_hmma_h<float><<<grid, 256, GEMM_SMEM>>>(xh_ptr, Ch_ptr, y, M, OUTD, ST);
    }
}

// round 17
// speedup vs baseline: 2.2494x; 1.0622x over previous
#include <cuda_runtime.h>
#include <cuda_fp16.h>
#include <cstdint>
#include <cstddef>

// Problem constants
#define BATCH 8
#define LEN   4096
#define IND   512
#define ST    256
#define OUTD  512

#define CHUNK 32
#define NCH   (LEN / CHUNK)   // 128

// Scratch in device globals (no allocation allowed)
__device__ half  g_uBh[(size_t)BATCH * LEN * ST];     // 16 MB (uB as fp16)
__device__ half  g_uh[(size_t)BATCH * LEN * IND];     // 32 MB (u as fp16)
__device__ half  g_xh[(size_t)BATCH * LEN * ST];      // 16 MB (x as fp16)
__device__ float g_carry[BATCH * NCH * ST];           // 1 MB
__device__ half  g_Bh[IND * ST];                      // B as fp16
__device__ half  g_Ch[ST * OUTD];                     // C as fp16

// ---------------------------------------------------------------------------
// HMMA single-pass fp16 GEMM:  Cm[M,N](OutT) = Ah[M,K](fp16) @ Bh[K,N](fp16)
// CTA tile 128x128x32, 8 warps as 2m x 4n, warp tile 64x32, fp32 accumulate.
// 3-stage cp.async pipeline, one __syncthreads per K-stage.
// If CARRY: epilogue also emits per-chunk scan carries
//   carry[b][c][n] = sum_{t in chunk} Av[n]^(31 - t_local) * acc[t][n]
// computed from the fp32 accumulators (M rows = time, 32-row chunks).
// ---------------------------------------------------------------------------
#define BM 128
#define BN 128
#define BKK 32
#define ALD 40    // A smem leading dim in halves (pad 32->40)
#define BLD 136   // B smem leading dim in halves (pad 128->136)
#define A_SZ (BM * ALD)                 // 5120 halves
#define B_SZ (BKK * BLD)                // 4352 halves
#define A_B  (A_SZ * 2)                 // 10240 bytes
#define B_B  (B_SZ * 2)                 // 8704 bytes
#define STAGE_B (A_B + B_B)             // 18944 bytes
#define NSTAGE 3
#define GEMM_SMEM (NSTAGE * STAGE_B)    // 56832 bytes

__device__ __forceinline__ uint32_t smem_u32(const void* p) {
    uint32_t a;
    asm("{ .reg .u64 t; cvta.to.shared.u64 t, %1; cvt.u32.u64 %0, t; }"
        : "=r"(a) : "l"(p));
    return a;
}

#define CP16(saddr, gptr) \
    asm volatile("cp.async.cg.shared.global [%0], [%1], 16;" \
        :: "r"(saddr), "l"(gptr))
#define CP_COMMIT() asm volatile("cp.async.commit_group;" ::: "memory")
#define CP_WAIT(n)  asm volatile("cp.async.wait_group %0;" :: "n"(n) : "memory")

#define LDSM_X4(r, addr) \
    asm volatile("ldmatrix.sync.aligned.m8n8.x4.shared.b16 {%0,%1,%2,%3}, [%4];" \
        : "=r"((r)[0]), "=r"((r)[1]), "=r"((r)[2]), "=r"((r)[3]) : "r"(addr))

#define LDSM_X4T(r, addr) \
    asm volatile("ldmatrix.sync.aligned.m8n8.x4.trans.shared.b16 {%0,%1,%2,%3}, [%4];" \
        : "=r"((r)[0]), "=r"((r)[1]), "=r"((r)[2]), "=r"((r)[3]) : "r"(addr))

#define MMA16816(d, a, b0, b1) \
    asm volatile("mma.sync.aligned.m16n8k16.row.col.f32.f16.f16.f32 " \
        "{%0,%1,%2,%3}, {%4,%5,%6,%7}, {%8,%9}, {%0,%1,%2,%3};" \
        : "+f"((d)[0]), "+f"((d)[1]), "+f"((d)[2]), "+f"((d)[3]) \
        : "r"((a)[0]), "r"((a)[1]), "r"((a)[2]), "r"((a)[3]), \
          "r"(b0), "r"(b1))

template <typename OutT, bool CARRY>
__global__ __launch_bounds__(256, 2)
void gemm_hmma_h(const half* __restrict__ Ag_, const half* __restrict__ Bhg,
                 OutT* __restrict__ Cm, const float* __restrict__ Av,
                 int M, int N, int K) {
    extern __shared__ half sm[];
    const uint32_t sbase = smem_u32(sm);
    const int tid = threadIdx.x;
    const int lane = tid & 31, wid = tid >> 5;
    const int warp_m = wid >> 2;  // 0..1  -> 64 rows each
    const int warp_n = wid & 3;   // 0..3  -> 32 cols each
    const int rowBase = blockIdx.y * BM;
    const int colBase = blockIdx.x * BN;

    // Staging maps: per thread 16 halves (2 x cp.async 16B) per tile
    const int ar = tid >> 1, ac = (tid & 1) * 16;   // A: 128 rows x 32 cols
    const int br = tid >> 3, bc = (tid & 7) * 16;   // B: 32 rows x 128 cols

    const half* Ag  = Ag_ + (size_t)(rowBase + ar) * K + ac;
    const half* Bg0 = Bhg + (size_t)br * N + colBase + bc;

    const uint32_t sAoff = (uint32_t)(ar * ALD + ac) * 2;
    const uint32_t sBoff = (uint32_t)A_B + (uint32_t)(br * BLD + bc) * 2;

    float acc[4][4][4] = {};

    const int nst = K / BKK;

    // prologue: stages 0 and 1
    #pragma unroll
    for (int p = 0; p < 2; p++) {
        uint32_t base = sbase + p * STAGE_B;
        const int k0 = p * BKK;
        const half* a  = Ag + k0;
        const half* b0 = Bg0 + (size_t)k0 * N;
        CP16(base + sAoff,      a);
        CP16(base + sAoff + 16, a + 8);
        CP16(base + sBoff,      b0);
        CP16(base + sBoff + 16, b0 + 8);
        CP_COMMIT();
    }

    int cur = 0;        // s % 3
    int nxt2 = 2;       // (s+2) % 3
    for (int s = 0; s < nst; s++) {
        CP_WAIT(1);         // stage s landed (FIFO completion)
        __syncthreads();    // stage s visible; stage s-1 compute done

        if (s + 2 < nst) {
            const int k0 = (s + 2) * BKK;
            uint32_t base = sbase + nxt2 * STAGE_B;
            const half* a  = Ag + k0;
            const half* b0 = Bg0 + (size_t)k0 * N;
            CP16(base + sAoff,      a);
            CP16(base + sAoff + 16, a + 8);
            CP16(base + sBoff,      b0);
            CP16(base + sBoff + 16, b0 + 8);
        }
        CP_COMMIT();        // always commit: uniform group counting

        // compute on stage cur
        {
            const uint32_t base = sbase + cur * STAGE_B;
            #pragma unroll
            for (int k16 = 0; k16 < 2; k16++) {
                uint32_t ah[4][4], bh[2][4];
                const int arow = warp_m * 64 + (lane & 15);
                const int acol = k16 * 16 + (lane >> 4) * 8;
                #pragma unroll
                for (int mi = 0; mi < 4; mi++)
                    LDSM_X4(ah[mi], base + (uint32_t)((arow + mi * 16) * ALD + acol) * 2);
                const int brow = k16 * 16 + (lane & 15);
                const int bcol = warp_n * 32 + (lane >> 4) * 8;
                #pragma unroll
                for (int ni = 0; ni < 2; ni++) {
                    uint32_t boff = (uint32_t)A_B + (uint32_t)(brow * BLD + bcol + ni * 16) * 2;
                    LDSM_X4T(bh[ni], base + boff);
                }
                #pragma unroll
                for (int mi = 0; mi < 4; mi++)
                    #pragma unroll
                    for (int nj = 0; nj < 4; nj++) {
                        const int ni = nj >> 1, ro = (nj & 1) * 2;
                        MMA16816(acc[mi][nj], ah[mi], bh[ni][ro], bh[ni][ro + 1]);
                    }
            }
        }

        cur = (cur == 2) ? 0 : cur + 1;
        nxt2 = (nxt2 == 2) ? 0 : nxt2 + 1;
    }

    // Epilogue: store C
    const int g = lane >> 2;
    const int cc = (lane & 3) * 2;
    #pragma unroll
    for (int mi = 0; mi < 4; mi++) {
        const int r0 = rowBase + warp_m * 64 + mi * 16 + g;
        #pragma unroll
        for (int nj = 0; nj < 4; nj++) {
            const int c0 = colBase + warp_n * 32 + nj * 8 + cc;
            if constexpr (sizeof(OutT) == 4) {
                *(float2*)&Cm[(size_t)r0 * N + c0] =
                    make_float2(acc[mi][nj][0], acc[mi][nj][1]);
                *(float2*)&Cm[(size_t)(r0 + 8) * N + c0] =
                    make_float2(acc[mi][nj][2], acc[mi][nj][3]);
            } else {
                *(half2*)&Cm[(size_t)r0 * N + c0] =
                    __floats2half2_rn(acc[mi][nj][0], acc[mi][nj][1]);
                *(half2*)&Cm[(size_t)(r0 + 8) * N + c0] =
                    __floats2half2_rn(acc[mi][nj][2], acc[mi][nj][3]);
            }
        }
    }

    // Epilogue: per-chunk scan carries (replaces scan1)
    if constexpr (CARRY) {
        const int e = 7 - g;    // wbase exponent: a^(7-g)
        #pragma unroll
        for (int ck = 0; ck < 2; ck++) {        // 2 chunks per warp
            const int grow = rowBase + warp_m * 64 + ck * 32;
            const int b = grow >> 12;           // / LEN(4096)
            const int cglob = (grow & (LEN - 1)) >> 5;
            #pragma unroll
            for (int nj = 0; nj < 4; nj++) {
                #pragma unroll
                for (int q = 0; q < 2; q++) {
                    const int col = colBase + warp_n * 32 + nj * 8 + cc + q;
                    const float a1 = Av[col];
                    const float a2 = a1 * a1, a4 = a2 * a2, a8 = a4 * a4;
                    float w = 1.0f;
                    if (e & 1) w *= a1;
                    if (e & 2) w *= a2;
                    if (e & 4) w *= a4;
                    // rows t_local = g, g+8, g+16, g+24
                    const float v0  = acc[ck * 2 + 0][nj][q];
                    const float v8  = acc[ck * 2 + 0][nj][q + 2];
                    const float v16 = acc[ck * 2 + 1][nj][q];
                    const float v24 = acc[ck * 2 + 1][nj][q + 2];
                    // carry = a^(31-g) v0 + a^(23-g) v8 + a^(15-g) v16 + a^(7-g) v24
                    float partial = w * (v24 + a8 * (v16 + a8 * (v8 + a8 * v0)));
                    #pragma unroll
                    for (int m = 4; m <= 16; m <<= 1)
                        partial += __shfl_xor_sync(0xffffffffu, partial, m);
                    if (g == 0)
                        g_carry[((size_t)b * NCH + cglob) * ST + col] = partial;
                }
            }
        }
    }
}

// ---------------------------------------------------------------------------
// Fused fp32 -> fp16 conversion of u, B, C in ONE launch (8 elems/thread).
// ---------------------------------------------------------------------------
#define NU ((size_t)BATCH * LEN * IND)   // 16777216
#define NB ((size_t)IND * ST)            // 131072
#define NC ((size_t)ST * OUTD)           // 131072

__global__ __launch_bounds__(256)
void cvt_all_kernel(const float* __restrict__ u, const float* __restrict__ B,
                    const float* __restrict__ C) {
    size_t i = ((size_t)blockIdx.x * 256 + threadIdx.x) * 8;
    const float* in;
    half* out;
    if (i < NU)           { in = u + i;            out = g_uh + i; }
    else if (i < NU + NB) { in = B + (i - NU);     out = g_Bh + (i - NU); }
    else                  { in = C + (i - NU - NB); out = g_Ch + (i - NU - NB); }
    float4 v0 = *(const float4*)in;
    float4 v1 = *(const float4*)(in + 4);
    half2 h[4];
    h[0] = __floats2half2_rn(v0.x, v0.y);
    h[1] = __floats2half2_rn(v0.z, v0.w);
    h[2] = __floats2half2_rn(v1.x, v1.y);
    h[3] = __floats2half2_rn(v1.z, v1.w);
    *(uint4*)out = *(uint4*)h;
}

// ---------------------------------------------------------------------------
// Scan pass (fused): each block (b,c) first computes its own init by
// prefix-scanning carries 0..c-1 (batch-16 register loads; carries are
// L2-resident), then rescans its chunk from init writing x as fp16.
// ---------------------------------------------------------------------------
#define S3P 16   // prefix batch
#define S1B 8    // rescan batch

__global__ __launch_bounds__(ST / 2)
void scan_kernel(const float* __restrict__ A, const float* __restrict__ x0,
                 float* __restrict__ xlast) {
    const int n2 = threadIdx.x;
    const int c = blockIdx.x % NCH;
    const int b = blockIdx.x / NCH;
    const float2 a = ((const float2*)A)[n2];
    float2 aL = a;
    #pragma unroll
    for (int i = 0; i < 5; i++) { aL.x *= aL.x; aL.y *= aL.y; }   // a^32

    // ---- local inter-chunk prefix: init = scan(x0, carries[0..c-1]) ----
    float2 s = ((const float2*)x0)[b * (ST / 2) + n2];
    const float2* carry = (const float2*)g_carry + (size_t)b * NCH * (ST / 2) + n2;
    int i = 0;
    for (; i + S3P <= c; i += S3P) {
        float2 buf[S3P];
        #pragma unroll
        for (int j = 0; j < S3P; j++)
            buf[j] = carry[(size_t)(i + j) * (ST / 2)];
        #pragma unroll
        for (int j = 0; j < S3P; j++) {
            s.x = fmaf(aL.x, s.x, buf[j].x);
            s.y = fmaf(aL.y, s.y, buf[j].y);
        }
    }
    {
        const int rem = c - i;     // 0..15
        float2 buf[S3P];
        #pragma unroll
        for (int j = 0; j < S3P; j++)
            if (j < rem) buf[j] = carry[(size_t)(i + j) * (ST / 2)];
        #pragma unroll
        for (int j = 0; j < S3P; j++)
            if (j < rem) {
                s.x = fmaf(aL.x, s.x, buf[j].x);
                s.y = fmaf(aL.y, s.y, buf[j].y);
            }
    }

    // ---- rescan this chunk from init, write x as fp16 ----
    const size_t base = ((size_t)(b * LEN + c * CHUNK)) * (ST / 2) + n2;
    const half2* pin = (const half2*)g_uBh;
    half2* pout = (half2*)g_xh;
    #pragma unroll
    for (int gq = 0; gq < CHUNK / S1B; gq++) {
        half2 buf[S1B];
        #pragma unroll
        for (int j = 0; j < S1B; j++)
            buf[j] = pin[base + (size_t)(gq * S1B + j) * (ST / 2)];
        #pragma unroll
        for (int j = 0; j < S1B; j++) {
            float2 v = __half22float2(buf[j]);
            s.x = fmaf(a.x, s.x, v.x);
            s.y = fmaf(a.y, s.y, v.y);
            pout[base + (size_t)(gq * S1B + j) * (ST / 2)] = __floats2half2_rn(s.x, s.y);
        }
    }
    if (c == NCH - 1) {
        ((float2*)xlast)[b * (ST / 2) + n2] = s;
    }
}

// ---------------------------------------------------------------------------
// kernel_launch
// Inputs: u [8,4096,512], x0 [8,256], A [256], B [512,256], C [256,512]
// Output: y [8,4096,512] flattened, then x_last [8,256].
// ---------------------------------------------------------------------------
extern "C" void kernel_launch(void* const* d_in, const int* in_sizes, int n_in,
                              void* d_out, int out_size) {
    const float* u  = (const float*)d_in[0];
    const float* x0 = (const float*)d_in[1];
    const float* A  = (const float*)d_in[2];
    const float* B  = (const float*)d_in[3];
    const float* C  = (const float*)d_in[4];

    float* y = (float*)d_out;
    float* xlast = y + (size_t)BATCH * LEN * OUTD;

    half *uBh_ptr, *uh_ptr, *xh_ptr, *Bh_ptr, *Ch_ptr;
    cudaGetSymbolAddress((void**)&uBh_ptr, g_uBh);
    cudaGetSymbolAddress((void**)&uh_ptr,  g_uh);
    cudaGetSymbolAddress((void**)&xh_ptr,  g_xh);
    cudaGetSymbolAddress((void**)&Bh_ptr,  g_Bh);
    cudaGetSymbolAddress((void**)&Ch_ptr,  g_Ch);

    cudaFuncSetAttribute((const void*)gemm_hmma_h<half, true>,
                         cudaFuncAttributeMaxDynamicSharedMemorySize, GEMM_SMEM);
    cudaFuncSetAttribute((const void*)gemm_hmma_h<float, false>,
                         cudaFuncAttributeMaxDynamicSharedMemorySize, GEMM_SMEM);

    const int M = BATCH * LEN;   // 32768

    // Fused pre-pass: u, B, C -> fp16 in one launch
    {
        size_t total = NU + NB + NC;
        cvt_all_kernel<<<(unsigned)(total / (256 * 8)), 256>>>(u, B, C);
    }

    // GEMM1 (+ per-chunk carries): uBh = uh @ Bh   [32768,512] @ [512,256]
    {
        dim3 grid(ST / BN, M / BM);
        gemm_hmma_h<half, true><<<grid, 256, GEMM_SMEM>>>(
            uh_ptr, Bh_ptr, uBh_ptr, A, M, ST, IND);
    }

    // Fused scan (prefix + rescan)
    scan_kernel<<<BATCH * NCH, ST / 2>>>(A, x0, xlast);

    // GEMM2: y = xh @ Ch    [32768,256] @ [256,512] -> fp32
    {
        dim3 grid(OUTD / BN, M / BM);
        gemm_hmma_h<float, false><<<grid, 256, GEMM_SMEM>>>(
            xh_ptr, Ch_ptr, y, nullptr, M, OUTD, ST);
    }
}